// round 11
// baseline (speedup 1.0000x reference)
#include <cuda_runtime.h>
#include <cuda_bf16.h>
#include <mma.h>
#include <float.h>
#include <cstdint>
using namespace nvcuda;

#define N_NODES 100000
#define N_EDGES 1000000
#define F_IN    128
#define F_HID   256
#define F_OUT   40
#define SCAN_B  98
#define PAD_ROWS 64

// ---------------- scratch ----------------------------------------------------
__device__ int   g_cnt   [N_NODES];
__device__ float g_dinv  [N_NODES];
__device__ int   g_srcA  [N_EDGES];
__device__ int   g_dstA  [N_EDGES];
__device__ int   g_rowptr[N_NODES + 1];
__device__ int   g_cursor[N_NODES];
__device__ __align__(16) int2 g_csr[N_EDGES];     // {src, w as float bits}
__device__ int   g_bsum[SCAN_B];
__device__ int   g_boff[SCAN_B];
// padded by PAD_ROWS so ragged-edge fragment loads stay in bounds
__device__ __align__(16) __nv_bfloat16 g_a1h[(size_t)(N_NODES + PAD_ROWS) * F_IN];
__device__ __align__(16) __nv_bfloat16 g_a1l[(size_t)(N_NODES + PAD_ROWS) * F_IN];
__device__ __align__(16) float g_h2 [(size_t)N_NODES * F_OUT];
__device__ __align__(16) __nv_bfloat16 g_w1h[128 * 256];   // [k][n] row-major
__device__ __align__(16) __nv_bfloat16 g_w1l[128 * 256];
__device__ __align__(16) __nv_bfloat16 g_w2h[256 * 48];    // [k][n48], n>=40 zero
__device__ __align__(16) __nv_bfloat16 g_w2l[256 * 48];
__device__ int   g_is32 = 0;   // sticky: dtype is fixed across replays

__device__ __forceinline__ void bsplit(float a, __nv_bfloat16& hi, __nv_bfloat16& lo) {
    hi = __float2bfloat16_rn(a);
    lo = __float2bfloat16_rn(a - __bfloat162float(hi));
}
__device__ __forceinline__ uint32_t pack_bf2(__nv_bfloat16 a, __nv_bfloat16 b) {
    __nv_bfloat162 t(a, b);
    return *(uint32_t*)&t;
}

// ---------------- fused: zero counts + dtype probe ----------------------------
__global__ void k_pre(const long long* __restrict__ e64) {
    int i = blockIdx.x * blockDim.x + threadIdx.x;
    if (i < N_NODES) g_cnt[i] = 0;
    if (blockIdx.x == 0) {
        for (int t = threadIdx.x; t < 8192; t += 256) {
            long long v = e64[(long long)t * 122];
            if (v < 0 || v >= N_NODES) g_is32 = 1;   // sticky across replays
        }
    }
}

__global__ void k_edges(const void* __restrict__ edge) {
    int e = blockIdx.x * blockDim.x + threadIdx.x;
    if (e >= N_EDGES) return;
    int s, d;
    if (g_is32) {
        const int* e32 = (const int*)edge;
        s = e32[e];  d = e32[N_EDGES + e];
    } else {
        const long long* e64 = (const long long*)edge;
        s = (int)e64[e];  d = (int)e64[N_EDGES + e];
    }
    g_srcA[e] = s;
    g_dstA[e] = d;
    atomicAdd(&g_cnt[d], 1);
}

// scan stage 1 (+ fused dinv)
__global__ __launch_bounds__(1024) void k_scan1() {
    __shared__ int wsum[32];
    int tid = threadIdx.x, lane = tid & 31, w = tid >> 5;
    int i = blockIdx.x * 1024 + tid;
    int v = 0;
    if (i < N_NODES) {
        v = g_cnt[i];
        g_dinv[i] = rsqrtf((float)(v + 1));
    }
    int r = v;
    #pragma unroll
    for (int o = 16; o; o >>= 1) r += __shfl_xor_sync(0xffffffffu, r, o);
    if (lane == 0) wsum[w] = r;
    __syncthreads();
    if (w == 0) {
        int y = wsum[lane];
        #pragma unroll
        for (int o = 16; o; o >>= 1) y += __shfl_xor_sync(0xffffffffu, y, o);
        if (lane == 0) g_bsum[blockIdx.x] = y;
    }
}

// parallel scan of the 98 block sums (1 block, 128 threads)
__global__ void k_scan2() {
    __shared__ int wsum[4];
    int tid = threadIdx.x, lane = tid & 31, w = tid >> 5;
    int v = (tid < SCAN_B) ? g_bsum[tid] : 0;
    int x = v;
    #pragma unroll
    for (int o = 1; o < 32; o <<= 1) {
        int y = __shfl_up_sync(0xffffffffu, x, o);
        if (lane >= o) x += y;
    }
    if (lane == 31) wsum[w] = x;
    __syncthreads();
    int base = 0;
    #pragma unroll
    for (int b = 0; b < 4; b++) base += (b < w) ? wsum[b] : 0;
    int incl = base + x;
    if (tid < SCAN_B) g_boff[tid] = incl - v;
    if (tid == SCAN_B - 1) g_rowptr[N_NODES] = incl;
}

__global__ __launch_bounds__(1024) void k_scan3() {
    __shared__ int wsum[32];
    int tid = threadIdx.x, lane = tid & 31, w = tid >> 5;
    int i = blockIdx.x * 1024 + tid;
    int v = (i < N_NODES) ? g_cnt[i] : 0;
    int x = v;
    #pragma unroll
    for (int o = 1; o < 32; o <<= 1) {
        int y = __shfl_up_sync(0xffffffffu, x, o);
        if (lane >= o) x += y;
    }
    if (lane == 31) wsum[w] = x;
    __syncthreads();
    if (w == 0) {
        int y = wsum[lane];
        #pragma unroll
        for (int o = 1; o < 32; o <<= 1) {
            int z = __shfl_up_sync(0xffffffffu, y, o);
            if (lane >= o) y += z;
        }
        wsum[lane] = y;
    }
    __syncthreads();
    if (i < N_NODES) {
        int off = g_boff[blockIdx.x] + x - v + (w > 0 ? wsum[w - 1] : 0);
        g_rowptr[i] = off;
        g_cursor[i] = off;
    }
}
__global__ void k_place() {
    int e = blockIdx.x * blockDim.x + threadIdx.x;
    if (e >= N_EDGES) return;
    int s = g_srcA[e], d = g_dstA[e];
    int pos = atomicAdd(&g_cursor[d], 1);
    float w = g_dinv[s] * g_dinv[d];
    g_csr[pos] = make_int2(s, __float_as_int(w));
}

// ---------------- weight prep (merged): bf16 split ----------------------------
__global__ void k_prep_w(const float* __restrict__ W1, const float* __restrict__ W2) {
    int i = blockIdx.x * blockDim.x + threadIdx.x;
    if (i < F_IN * F_HID) {                       // W1: i = k*256 + n
        __nv_bfloat16 h, l;
        bsplit(W1[i], h, l);
        g_w1h[i] = h;
        g_w1l[i] = l;
    }
    int j = i - F_IN * F_HID;
    if (j >= 0 && j < 48 * F_HID) {               // W2: j = k*48 + n
        int k = j / 48, n = j - k * 48;
        float v = (n < F_OUT) ? W2[(size_t)k * F_OUT + n] : 0.f;
        __nv_bfloat16 h, l;
        bsplit(v, h, l);
        g_w2h[j] = h;
        g_w2l[j] = l;
    }
}

// ---------------- layer-1 aggregation (CSR, warp per dst) -> bf16 hi/lo ------
__global__ void k_agg1(const float* __restrict__ x) {
    int t    = blockIdx.x * blockDim.x + threadIdx.x;
    int d    = t >> 5;
    int lane = t & 31;
    if (d >= N_NODES) return;
    const float4* x4 = (const float4*)x;
    float dv = g_dinv[d];
    float d2 = dv * dv;
    float4 v = x4[(size_t)d * 32 + lane];
    float4 acc = make_float4(v.x * d2, v.y * d2, v.z * d2, v.w * d2);
    int p0 = g_rowptr[d], p1 = g_rowptr[d + 1];
    int p = p0;
    for (; p + 3 < p1; p += 4) {                 // 4-way MLP
        int2 e0 = g_csr[p],     e1 = g_csr[p + 1];
        int2 e2 = g_csr[p + 2], e3 = g_csr[p + 3];
        float w0 = __int_as_float(e0.y), w1 = __int_as_float(e1.y);
        float w2 = __int_as_float(e2.y), w3 = __int_as_float(e3.y);
        float4 u0 = x4[(size_t)e0.x * 32 + lane];
        float4 u1 = x4[(size_t)e1.x * 32 + lane];
        float4 u2 = x4[(size_t)e2.x * 32 + lane];
        float4 u3 = x4[(size_t)e3.x * 32 + lane];
        acc.x += w0 * u0.x + w1 * u1.x + w2 * u2.x + w3 * u3.x;
        acc.y += w0 * u0.y + w1 * u1.y + w2 * u2.y + w3 * u3.y;
        acc.z += w0 * u0.z + w1 * u1.z + w2 * u2.z + w3 * u3.z;
        acc.w += w0 * u0.w + w1 * u1.w + w2 * u2.w + w3 * u3.w;
    }
    for (; p < p1; p++) {
        int2 e = g_csr[p];
        float w = __int_as_float(e.y);
        float4 u = x4[(size_t)e.x * 32 + lane];
        acc.x += w * u.x; acc.y += w * u.y;
        acc.z += w * u.z; acc.w += w * u.w;
    }
    __nv_bfloat16 h0, l0, h1, l1, h2, l2, h3, l3;
    bsplit(acc.x, h0, l0); bsplit(acc.y, h1, l1);
    bsplit(acc.z, h2, l2); bsplit(acc.w, h3, l3);
    size_t base = (size_t)d * F_IN + lane * 4;
    *(uint32_t*)&g_a1h[base]     = pack_bf2(h0, h1);
    *(uint32_t*)&g_a1h[base + 2] = pack_bf2(h2, h3);
    *(uint32_t*)&g_a1l[base]     = pack_bf2(l0, l1);
    *(uint32_t*)&g_a1l[base + 2] = pack_bf2(l2, l3);
}

// ---------------- fused MLP: h2 = relu(agg1@W1+b1) @ W2 ----------------------
// 64 rows/block, 256 threads (8 warps). Split-bf16 (3 MMAs) both GEMMs.
// A (agg1) and W1/W2 fragments loaded DIRECTLY from global (L1-resident) —
// no smem staging, no phase-A barriers. Only one __syncthreads (H handoff).
// smem: H hi/lo 67584 + stg 8192 = 75776 bytes -> 2 CTAs/SM with headroom.
#define SM_H     0
#define SM_STG   67584
#define MLP_SMEM 75776

__global__ __launch_bounds__(256, 2) void k_mlp(const float* __restrict__ b1) {
    extern __shared__ char sm[];
    __nv_bfloat16* Hh = (__nv_bfloat16*)(sm + SM_H);
    __nv_bfloat16* Hl = (__nv_bfloat16*)(sm + SM_H + 33792);
    float*         stg = (float*)(sm + SM_STG);

    int tid = threadIdx.x, wid = tid >> 5, lane = tid & 31;
    int bm = blockIdx.x * 64;
    int rg = wid >> 1, cg = wid & 1;     // 4 row-groups x 2 col-groups

    // ---- phase A: H = relu(A @ W1 + b1); all operands via global/L1 ----
    wmma::fragment<wmma::accumulator, 16, 16, 16, float> acc[8];
    #pragma unroll
    for (int j = 0; j < 8; j++) wmma::fill_fragment(acc[j], 0.f);

    const __nv_bfloat16* Arow_h = g_a1h + (size_t)(bm + rg * 16) * F_IN;
    const __nv_bfloat16* Arow_l = g_a1l + (size_t)(bm + rg * 16) * F_IN;

    #pragma unroll
    for (int k = 0; k < 8; k++) {
        wmma::fragment<wmma::matrix_a, 16, 16, 16, __nv_bfloat16, wmma::row_major> ah, al;
        wmma::load_matrix_sync(ah, Arow_h + k * 16, F_IN);
        wmma::load_matrix_sync(al, Arow_l + k * 16, F_IN);
        #pragma unroll
        for (int j = 0; j < 8; j++) {
            int nc = cg * 128 + j * 16;
            wmma::fragment<wmma::matrix_b, 16, 16, 16, __nv_bfloat16, wmma::row_major> bh, bl;
            wmma::load_matrix_sync(bh, g_w1h + (k * 16) * 256 + nc, 256);
            wmma::load_matrix_sync(bl, g_w1l + (k * 16) * 256 + nc, 256);
            wmma::mma_sync(acc[j], ah, bh, acc[j]);
            wmma::mma_sync(acc[j], ah, bl, acc[j]);
            wmma::mma_sync(acc[j], al, bh, acc[j]);
        }
    }

    // ---- epilogue A: bias + relu + split -> H smem ----
    #pragma unroll
    for (int j = 0; j < 8; j++) {
        wmma::store_matrix_sync(&stg[wid * 256], acc[j], 16, wmma::mem_row_major);
        __syncwarp();
        int r  = lane >> 1, c0 = (lane & 1) * 8;
        int col = cg * 128 + j * 16 + c0;
        uint32_t hw[4], lw[4];
        #pragma unroll
        for (int e = 0; e < 8; e += 2) {
            float f0 = fmaxf(stg[wid * 256 + r * 16 + c0 + e]     + b1[col + e],     0.f);
            float f1 = fmaxf(stg[wid * 256 + r * 16 + c0 + e + 1] + b1[col + e + 1], 0.f);
            __nv_bfloat16 h0, l0, h1, l1;
            bsplit(f0, h0, l0); bsplit(f1, h1, l1);
            hw[e >> 1] = pack_bf2(h0, h1);
            lw[e >> 1] = pack_bf2(l0, l1);
        }
        int row = rg * 16 + r;
        *(uint4*)&Hh[row * 264 + col] = *(uint4*)hw;
        *(uint4*)&Hl[row * 264 + col] = *(uint4*)lw;
        __syncwarp();
    }
    __syncthreads();     // the only block-wide barrier: H handoff

    // ---- phase B: H2 = H @ W2 (N padded to 48: cg0 -> 2 tiles, cg1 -> 1) ----
    int nTiles = (cg == 0) ? 2 : 1;
    wmma::fragment<wmma::accumulator, 16, 16, 16, float> acc2[2];
    #pragma unroll
    for (int j = 0; j < 2; j++) wmma::fill_fragment(acc2[j], 0.f);

    #pragma unroll
    for (int k = 0; k < 16; k++) {
        wmma::fragment<wmma::matrix_a, 16, 16, 16, __nv_bfloat16, wmma::row_major> ah, al;
        wmma::load_matrix_sync(ah, &Hh[(rg * 16) * 264 + k * 16], 264);
        wmma::load_matrix_sync(al, &Hl[(rg * 16) * 264 + k * 16], 264);
        for (int j = 0; j < nTiles; j++) {
            int nc = (cg == 0) ? j * 16 : 32;
            wmma::fragment<wmma::matrix_b, 16, 16, 16, __nv_bfloat16, wmma::row_major> bh, bl;
            wmma::load_matrix_sync(bh, g_w2h + (k * 16) * 48 + nc, 48);
            wmma::load_matrix_sync(bl, g_w2l + (k * 16) * 48 + nc, 48);
            wmma::mma_sync(acc2[j], ah, bh, acc2[j]);
            wmma::mma_sync(acc2[j], ah, bl, acc2[j]);
            wmma::mma_sync(acc2[j], al, bh, acc2[j]);
        }
    }

    // ---- epilogue B: write h2 (cols < 40) ----
    for (int j = 0; j < nTiles; j++) {
        int ncb = (cg == 0) ? j * 16 : 32;
        wmma::store_matrix_sync(&stg[wid * 256], acc2[j], 16, wmma::mem_row_major);
        __syncwarp();
        int r  = lane >> 1, c0 = (lane & 1) * 8;
        int row = bm + rg * 16 + r;
        int col = ncb + c0;
        if (row < N_NODES && col < F_OUT) {
            float* dst = g_h2 + (size_t)row * F_OUT + col;
            *(float4*)(dst)     = *(float4*)&stg[wid * 256 + r * 16 + c0];
            *(float4*)(dst + 4) = *(float4*)&stg[wid * 256 + r * 16 + c0 + 4];
        }
        __syncwarp();
    }
}

// ---------------- layer-2 aggregation + bias + log_softmax (fused) -----------
// 2 dst per warp (16-lane halves); lanes q<10 own one float4 each.
__global__ void k_layer2(const float* __restrict__ b2, float* __restrict__ out) {
    int t    = blockIdx.x * blockDim.x + threadIdx.x;
    int warp = t >> 5;
    int lane = t & 31;
    int half = lane >> 4;
    int q    = lane & 15;
    int d    = warp * 2 + half;
    const float4* h4 = (const float4*)g_h2;
    bool inb    = d < N_NODES;
    bool active = inb && (q < 10);

    float d2 = 0.f; int p0 = 0, p1 = 0;
    if (inb) {
        float dv = g_dinv[d];
        d2 = dv * dv;
        p0 = g_rowptr[d]; p1 = g_rowptr[d + 1];
    }
    float4 acc = make_float4(0.f, 0.f, 0.f, 0.f);
    if (active) {
        float4 v  = h4[(size_t)d * 10 + q];
        float4 bb = ((const float4*)b2)[q];
        acc.x = v.x * d2 + bb.x; acc.y = v.y * d2 + bb.y;
        acc.z = v.z * d2 + bb.z; acc.w = v.w * d2 + bb.w;
    }
    int p = p0;
    for (; p + 1 < p1; p += 2) {
        int2 e0 = g_csr[p], e1 = g_csr[p + 1];
        float w0 = __int_as_float(e0.y), w1 = __int_as_float(e1.y);
        if (active) {
            float4 u0 = h4[(size_t)e0.x * 10 + q];
            float4 u1 = h4[(size_t)e1.x * 10 + q];
            acc.x += w0 * u0.x + w1 * u1.x;
            acc.y += w0 * u0.y + w1 * u1.y;
            acc.z += w0 * u0.z + w1 * u1.z;
            acc.w += w0 * u0.w + w1 * u1.w;
        }
    }
    if (p < p1) {
        int2 e = g_csr[p];
        float w = __int_as_float(e.y);
        if (active) {
            float4 u = h4[(size_t)e.x * 10 + q];
            acc.x += w * u.x; acc.y += w * u.y;
            acc.z += w * u.z; acc.w += w * u.w;
        }
    }
    float m = active ? fmaxf(fmaxf(acc.x, acc.y), fmaxf(acc.z, acc.w)) : -FLT_MAX;
    #pragma unroll
    for (int o = 8; o; o >>= 1) m = fmaxf(m, __shfl_xor_sync(0xffffffffu, m, o, 16));
    float s = active ? (expf(acc.x - m) + expf(acc.y - m) +
                        expf(acc.z - m) + expf(acc.w - m)) : 0.f;
    #pragma unroll
    for (int o = 8; o; o >>= 1) s += __shfl_xor_sync(0xffffffffu, s, o, 16);
    float l = m + logf(s);
    if (active) {
        ((float4*)out)[(size_t)d * 10 + q] =
            make_float4(acc.x - l, acc.y - l, acc.z - l, acc.w - l);
    }
}

// ---------------- launch ------------------------------------------------------
extern "C" void kernel_launch(void* const* d_in, const int* in_sizes, int n_in,
                              void* d_out, int out_size) {
    const float* x    = (const float*)d_in[0];
    const void*  edge = d_in[1];
    const float* W1   = (const float*)d_in[2];
    const float* b1   = (const float*)d_in[3];
    const float* W2   = (const float*)d_in[4];
    const float* b2   = (const float*)d_in[5];
    float*       out  = (float*)d_out;

    cudaFuncSetAttribute(k_mlp, cudaFuncAttributeMaxDynamicSharedMemorySize, MLP_SMEM);

    k_pre      <<<(N_NODES + 255) / 256, 256>>>((const long long*)edge);
    k_edges    <<<(N_EDGES + 255) / 256, 256>>>(edge);
    k_scan1    <<<SCAN_B, 1024>>>();
    k_scan2    <<<1, 128>>>();
    k_scan3    <<<SCAN_B, 1024>>>();
    k_place    <<<(N_EDGES + 255) / 256, 256>>>();
    k_prep_w   <<<(F_IN * F_HID + 48 * F_HID + 255) / 256, 256>>>(W1, W2);
    k_agg1     <<<(N_NODES * 32 + 255) / 256, 256>>>(x);
    k_mlp      <<<(N_NODES + 63) / 64, 256, MLP_SMEM>>>(b1);
    k_layer2   <<<(N_NODES / 2 * 32 + 255) / 256, 256>>>(b2, out);
}

// round 12
// speedup vs baseline: 1.4615x; 1.4615x over previous
#include <cuda_runtime.h>
#include <cuda_bf16.h>
#include <mma.h>
#include <float.h>
#include <cstdint>
using namespace nvcuda;

#define N_NODES 100000
#define N_EDGES 1000000
#define F_IN    128
#define F_HID   256
#define F_OUT   40
#define SCAN_B  98
#define PAD_ROWS 64

// ---------------- scratch ----------------------------------------------------
__device__ int   g_cnt   [N_NODES];
__device__ float g_dinv  [N_NODES];
__device__ int   g_srcA  [N_EDGES];
__device__ int   g_dstA  [N_EDGES];
__device__ int   g_rowptr[N_NODES + 1];
__device__ int   g_cursor[N_NODES];
__device__ __align__(16) int2 g_csr[N_EDGES];     // {src, w as float bits}
__device__ int   g_bsum[SCAN_B];
__device__ int   g_boff[SCAN_B];
__device__ __align__(16) __nv_bfloat16 g_a1h[(size_t)(N_NODES + PAD_ROWS) * F_IN];
__device__ __align__(16) __nv_bfloat16 g_a1l[(size_t)(N_NODES + PAD_ROWS) * F_IN];
__device__ __align__(16) float g_h2 [(size_t)N_NODES * F_OUT];
__device__ __align__(16) __nv_bfloat16 g_w1h[128 * 256];   // [k][n] row-major
__device__ __align__(16) __nv_bfloat16 g_w1l[128 * 256];
__device__ __align__(16) __nv_bfloat16 g_w2h[256 * 48];    // [k][n48], n>=40 zero
__device__ __align__(16) __nv_bfloat16 g_w2l[256 * 48];
__device__ int   g_is32 = 0;   // sticky: dtype is fixed across replays

__device__ __forceinline__ void bsplit(float a, __nv_bfloat16& hi, __nv_bfloat16& lo) {
    hi = __float2bfloat16_rn(a);
    lo = __float2bfloat16_rn(a - __bfloat162float(hi));
}
__device__ __forceinline__ uint32_t pack_bf2(__nv_bfloat16 a, __nv_bfloat16 b) {
    __nv_bfloat162 t(a, b);
    return *(uint32_t*)&t;
}

// ---------------- fused: zero counts + dtype probe ----------------------------
__global__ void k_pre(const long long* __restrict__ e64) {
    int i = blockIdx.x * blockDim.x + threadIdx.x;
    if (i < N_NODES) g_cnt[i] = 0;
    if (blockIdx.x == 0) {
        for (int t = threadIdx.x; t < 8192; t += 256) {
            long long v = e64[(long long)t * 122];
            if (v < 0 || v >= N_NODES) g_is32 = 1;   // sticky across replays
        }
    }
}

__global__ void k_edges(const void* __restrict__ edge) {
    int e = blockIdx.x * blockDim.x + threadIdx.x;
    if (e >= N_EDGES) return;
    int s, d;
    if (g_is32) {
        const int* e32 = (const int*)edge;
        s = e32[e];  d = e32[N_EDGES + e];
    } else {
        const long long* e64 = (const long long*)edge;
        s = (int)e64[e];  d = (int)e64[N_EDGES + e];
    }
    g_srcA[e] = s;
    g_dstA[e] = d;
    atomicAdd(&g_cnt[d], 1);
}

// scan stage 1 (+ fused dinv)
__global__ __launch_bounds__(1024) void k_scan1() {
    __shared__ int wsum[32];
    int tid = threadIdx.x, lane = tid & 31, w = tid >> 5;
    int i = blockIdx.x * 1024 + tid;
    int v = 0;
    if (i < N_NODES) {
        v = g_cnt[i];
        g_dinv[i] = rsqrtf((float)(v + 1));
    }
    int r = v;
    #pragma unroll
    for (int o = 16; o; o >>= 1) r += __shfl_xor_sync(0xffffffffu, r, o);
    if (lane == 0) wsum[w] = r;
    __syncthreads();
    if (w == 0) {
        int y = wsum[lane];
        #pragma unroll
        for (int o = 16; o; o >>= 1) y += __shfl_xor_sync(0xffffffffu, y, o);
        if (lane == 0) g_bsum[blockIdx.x] = y;
    }
}

// parallel scan of the 98 block sums (1 block, 128 threads)
__global__ void k_scan2() {
    __shared__ int wsum[4];
    int tid = threadIdx.x, lane = tid & 31, w = tid >> 5;
    int v = (tid < SCAN_B) ? g_bsum[tid] : 0;
    int x = v;
    #pragma unroll
    for (int o = 1; o < 32; o <<= 1) {
        int y = __shfl_up_sync(0xffffffffu, x, o);
        if (lane >= o) x += y;
    }
    if (lane == 31) wsum[w] = x;
    __syncthreads();
    int base = 0;
    #pragma unroll
    for (int b = 0; b < 4; b++) base += (b < w) ? wsum[b] : 0;
    int incl = base + x;
    if (tid < SCAN_B) g_boff[tid] = incl - v;
    if (tid == SCAN_B - 1) g_rowptr[N_NODES] = incl;
}

__global__ __launch_bounds__(1024) void k_scan3() {
    __shared__ int wsum[32];
    int tid = threadIdx.x, lane = tid & 31, w = tid >> 5;
    int i = blockIdx.x * 1024 + tid;
    int v = (i < N_NODES) ? g_cnt[i] : 0;
    int x = v;
    #pragma unroll
    for (int o = 1; o < 32; o <<= 1) {
        int y = __shfl_up_sync(0xffffffffu, x, o);
        if (lane >= o) x += y;
    }
    if (lane == 31) wsum[w] = x;
    __syncthreads();
    if (w == 0) {
        int y = wsum[lane];
        #pragma unroll
        for (int o = 1; o < 32; o <<= 1) {
            int z = __shfl_up_sync(0xffffffffu, y, o);
            if (lane >= o) y += z;
        }
        wsum[lane] = y;
    }
    __syncthreads();
    if (i < N_NODES) {
        int off = g_boff[blockIdx.x] + x - v + (w > 0 ? wsum[w - 1] : 0);
        g_rowptr[i] = off;
        g_cursor[i] = off;
    }
}
__global__ void k_place() {
    int e = blockIdx.x * blockDim.x + threadIdx.x;
    if (e >= N_EDGES) return;
    int s = g_srcA[e], d = g_dstA[e];
    int pos = atomicAdd(&g_cursor[d], 1);
    float w = g_dinv[s] * g_dinv[d];
    g_csr[pos] = make_int2(s, __float_as_int(w));
}

// ---------------- weight prep (merged): bf16 split ----------------------------
__global__ void k_prep_w(const float* __restrict__ W1, const float* __restrict__ W2) {
    int i = blockIdx.x * blockDim.x + threadIdx.x;
    if (i < F_IN * F_HID) {                       // W1: i = k*256 + n
        __nv_bfloat16 h, l;
        bsplit(W1[i], h, l);
        g_w1h[i] = h;
        g_w1l[i] = l;
    }
    int j = i - F_IN * F_HID;
    if (j >= 0 && j < 48 * F_HID) {               // W2: j = k*48 + n
        int k = j / 48, n = j - k * 48;
        float v = (n < F_OUT) ? W2[(size_t)k * F_OUT + n] : 0.f;
        __nv_bfloat16 h, l;
        bsplit(v, h, l);
        g_w2h[j] = h;
        g_w2l[j] = l;
    }
}

// ---------------- layer-1 aggregation (CSR, warp per dst) -> bf16 hi/lo ------
__global__ void k_agg1(const float* __restrict__ x) {
    int t    = blockIdx.x * blockDim.x + threadIdx.x;
    int d    = t >> 5;
    int lane = t & 31;
    if (d >= N_NODES) return;
    const float4* x4 = (const float4*)x;
    float dv = g_dinv[d];
    float d2 = dv * dv;
    float4 v = x4[(size_t)d * 32 + lane];
    float4 acc = make_float4(v.x * d2, v.y * d2, v.z * d2, v.w * d2);
    int p0 = g_rowptr[d], p1 = g_rowptr[d + 1];
    int p = p0;
    for (; p + 3 < p1; p += 4) {                 // 4-way MLP
        int2 e0 = g_csr[p],     e1 = g_csr[p + 1];
        int2 e2 = g_csr[p + 2], e3 = g_csr[p + 3];
        float w0 = __int_as_float(e0.y), w1 = __int_as_float(e1.y);
        float w2 = __int_as_float(e2.y), w3 = __int_as_float(e3.y);
        float4 u0 = x4[(size_t)e0.x * 32 + lane];
        float4 u1 = x4[(size_t)e1.x * 32 + lane];
        float4 u2 = x4[(size_t)e2.x * 32 + lane];
        float4 u3 = x4[(size_t)e3.x * 32 + lane];
        acc.x += w0 * u0.x + w1 * u1.x + w2 * u2.x + w3 * u3.x;
        acc.y += w0 * u0.y + w1 * u1.y + w2 * u2.y + w3 * u3.y;
        acc.z += w0 * u0.z + w1 * u1.z + w2 * u2.z + w3 * u3.z;
        acc.w += w0 * u0.w + w1 * u1.w + w2 * u2.w + w3 * u3.w;
    }
    for (; p < p1; p++) {
        int2 e = g_csr[p];
        float w = __int_as_float(e.y);
        float4 u = x4[(size_t)e.x * 32 + lane];
        acc.x += w * u.x; acc.y += w * u.y;
        acc.z += w * u.z; acc.w += w * u.w;
    }
    __nv_bfloat16 h0, l0, h1, l1, h2, l2, h3, l3;
    bsplit(acc.x, h0, l0); bsplit(acc.y, h1, l1);
    bsplit(acc.z, h2, l2); bsplit(acc.w, h3, l3);
    size_t base = (size_t)d * F_IN + lane * 4;
    *(uint32_t*)&g_a1h[base]     = pack_bf2(h0, h1);
    *(uint32_t*)&g_a1h[base + 2] = pack_bf2(h2, h3);
    *(uint32_t*)&g_a1l[base]     = pack_bf2(l0, l1);
    *(uint32_t*)&g_a1l[base + 2] = pack_bf2(l2, l3);
}

// ---------------- fused MLP: h2 = relu(agg1@W1+b1) @ W2 ----------------------
// R10 champion structure: 64 rows/block, 256 threads, smem staging + LDSM,
// W1 double-buffered 2 k-tiles deep, smem aliasing for 2 CTAs/SM.
#define SM_H    0
#define SM_A    67584
#define MLP_SMEM 102400

__device__ __forceinline__ void stage_b1(char* sm, int buf, int sub, int k, int tid) {
    __nv_bfloat16* Bh = (__nv_bfloat16*)(sm + SM_H + buf * 33792 + sub * 16896);
    __nv_bfloat16* Bl = (__nv_bfloat16*)(sm + SM_H + buf * 33792 + sub * 16896 + 8448);
    #pragma unroll
    for (int u = tid; u < 512; u += 256) {
        int r = u >> 5, c8 = (u & 31) << 3;
        *(uint4*)&Bh[r * 264 + c8] = *(const uint4*)&g_w1h[(k * 16 + r) * 256 + c8];
        *(uint4*)&Bl[r * 264 + c8] = *(const uint4*)&g_w1l[(k * 16 + r) * 256 + c8];
    }
}

__global__ __launch_bounds__(256, 2) void k_mlp(const float* __restrict__ b1) {
    extern __shared__ char sm[];
    __nv_bfloat16* Hh = (__nv_bfloat16*)(sm + SM_H);
    __nv_bfloat16* Hl = (__nv_bfloat16*)(sm + SM_H + 33792);
    __nv_bfloat16* Ah = (__nv_bfloat16*)(sm + SM_A);
    __nv_bfloat16* Al = (__nv_bfloat16*)(sm + SM_A + 17408);
    float*         stg = (float*)(sm + SM_A);      // aliases A (dead in epilogues)

    int tid = threadIdx.x, wid = tid >> 5, lane = tid & 31;
    int bm = blockIdx.x * 64;
    int rg = wid >> 1, cg = wid & 1;     // 4 row-groups x 2 col-groups

    // ---- load A (64 x 128) hi/lo ----
    for (int u = tid; u < 1024; u += 256) {
        int r = u >> 4, c8 = (u & 15) << 3;
        uint4 vh = make_uint4(0, 0, 0, 0), vl = make_uint4(0, 0, 0, 0);
        int gr = bm + r;
        if (gr < N_NODES) {
            vh = *(const uint4*)&g_a1h[(size_t)gr * F_IN + c8];
            vl = *(const uint4*)&g_a1l[(size_t)gr * F_IN + c8];
        }
        *(uint4*)&Ah[r * 136 + c8] = vh;
        *(uint4*)&Al[r * 136 + c8] = vl;
    }
    stage_b1(sm, 0, 0, 0, tid);
    stage_b1(sm, 0, 1, 1, tid);
    __syncthreads();

    // ---- phase A: H = relu(A @ W1 + b1), W1 double-buffered 2 k-tiles deep --
    wmma::fragment<wmma::accumulator, 16, 16, 16, float> acc[8];
    #pragma unroll
    for (int j = 0; j < 8; j++) wmma::fill_fragment(acc[j], 0.f);

    #pragma unroll
    for (int t2 = 0; t2 < 4; t2++) {              // pairs of k-steps
        int cur = t2 & 1;
        if (t2 < 3) {
            stage_b1(sm, 1 - cur, 0, 2 * t2 + 2, tid);
            stage_b1(sm, 1 - cur, 1, 2 * t2 + 3, tid);
        }
        #pragma unroll
        for (int kk = 0; kk < 2; kk++) {
            int k = 2 * t2 + kk;
            __nv_bfloat16* B1h = (__nv_bfloat16*)(sm + SM_H + cur * 33792 + kk * 16896);
            __nv_bfloat16* B1l = (__nv_bfloat16*)(sm + SM_H + cur * 33792 + kk * 16896 + 8448);

            wmma::fragment<wmma::matrix_a, 16, 16, 16, __nv_bfloat16, wmma::row_major> ah, al;
            wmma::load_matrix_sync(ah, &Ah[(rg * 16) * 136 + k * 16], 136);
            wmma::load_matrix_sync(al, &Al[(rg * 16) * 136 + k * 16], 136);
            #pragma unroll
            for (int j = 0; j < 8; j++) {
                wmma::fragment<wmma::matrix_b, 16, 16, 16, __nv_bfloat16, wmma::row_major> bh, bl;
                wmma::load_matrix_sync(bh, &B1h[cg * 128 + j * 16], 264);
                wmma::load_matrix_sync(bl, &B1l[cg * 128 + j * 16], 264);
                wmma::mma_sync(acc[j], ah, bh, acc[j]);
                wmma::mma_sync(acc[j], ah, bl, acc[j]);
                wmma::mma_sync(acc[j], al, bh, acc[j]);
            }
        }
        __syncthreads();
    }

    // ---- epilogue A: bias + relu + split -> H smem ----
    #pragma unroll
    for (int j = 0; j < 8; j++) {
        wmma::store_matrix_sync(&stg[wid * 256], acc[j], 16, wmma::mem_row_major);
        __syncwarp();
        int r  = lane >> 1, c0 = (lane & 1) * 8;
        int col = cg * 128 + j * 16 + c0;
        uint32_t hw[4], lw[4];
        #pragma unroll
        for (int e = 0; e < 8; e += 2) {
            float f0 = fmaxf(stg[wid * 256 + r * 16 + c0 + e]     + b1[col + e],     0.f);
            float f1 = fmaxf(stg[wid * 256 + r * 16 + c0 + e + 1] + b1[col + e + 1], 0.f);
            __nv_bfloat16 h0, l0, h1, l1;
            bsplit(f0, h0, l0); bsplit(f1, h1, l1);
            hw[e >> 1] = pack_bf2(h0, h1);
            lw[e >> 1] = pack_bf2(l0, l1);
        }
        int row = rg * 16 + r;
        *(uint4*)&Hh[row * 264 + col] = *(uint4*)hw;
        *(uint4*)&Hl[row * 264 + col] = *(uint4*)lw;
        __syncwarp();
    }
    __syncthreads();

    // ---- phase B: H2 = H @ W2 (N padded to 48: cg0 -> 2 tiles, cg1 -> 1) ----
    int nTiles = (cg == 0) ? 2 : 1;
    wmma::fragment<wmma::accumulator, 16, 16, 16, float> acc2[2];
    #pragma unroll
    for (int j = 0; j < 2; j++) wmma::fill_fragment(acc2[j], 0.f);

    #pragma unroll
    for (int k = 0; k < 16; k++) {
        wmma::fragment<wmma::matrix_a, 16, 16, 16, __nv_bfloat16, wmma::row_major> ah, al;
        wmma::load_matrix_sync(ah, &Hh[(rg * 16) * 264 + k * 16], 264);
        wmma::load_matrix_sync(al, &Hl[(rg * 16) * 264 + k * 16], 264);
        for (int j = 0; j < nTiles; j++) {
            int nc = (cg == 0) ? j * 16 : 32;
            wmma::fragment<wmma::matrix_b, 16, 16, 16, __nv_bfloat16, wmma::row_major> bh, bl;
            wmma::load_matrix_sync(bh, g_w2h + (k * 16) * 48 + nc, 48);
            wmma::load_matrix_sync(bl, g_w2l + (k * 16) * 48 + nc, 48);
            wmma::mma_sync(acc2[j], ah, bh, acc2[j]);
            wmma::mma_sync(acc2[j], ah, bl, acc2[j]);
            wmma::mma_sync(acc2[j], al, bh, acc2[j]);
        }
    }

    // ---- epilogue B: write h2 (cols < 40) ----
    for (int j = 0; j < nTiles; j++) {
        int ncb = (cg == 0) ? j * 16 : 32;
        wmma::store_matrix_sync(&stg[wid * 256], acc2[j], 16, wmma::mem_row_major);
        __syncwarp();
        int r  = lane >> 1, c0 = (lane & 1) * 8;
        int row = bm + rg * 16 + r;
        int col = ncb + c0;
        if (row < N_NODES && col < F_OUT) {
            float* dst = g_h2 + (size_t)row * F_OUT + col;
            *(float4*)(dst)     = *(float4*)&stg[wid * 256 + r * 16 + c0];
            *(float4*)(dst + 4) = *(float4*)&stg[wid * 256 + r * 16 + c0 + 4];
        }
        __syncwarp();
    }
}

// ---------------- layer-2 aggregation + bias + log_softmax (fused) -----------
// 2 dst per warp (16-lane halves); lanes q<10 own one float4 each.
__global__ void k_layer2(const float* __restrict__ b2, float* __restrict__ out) {
    int t    = blockIdx.x * blockDim.x + threadIdx.x;
    int warp = t >> 5;
    int lane = t & 31;
    int half = lane >> 4;
    int q    = lane & 15;
    int d    = warp * 2 + half;
    const float4* h4 = (const float4*)g_h2;
    bool inb    = d < N_NODES;
    bool active = inb && (q < 10);

    float d2 = 0.f; int p0 = 0, p1 = 0;
    if (inb) {
        float dv = g_dinv[d];
        d2 = dv * dv;
        p0 = g_rowptr[d]; p1 = g_rowptr[d + 1];
    }
    float4 acc = make_float4(0.f, 0.f, 0.f, 0.f);
    if (active) {
        float4 v  = h4[(size_t)d * 10 + q];
        float4 bb = ((const float4*)b2)[q];
        acc.x = v.x * d2 + bb.x; acc.y = v.y * d2 + bb.y;
        acc.z = v.z * d2 + bb.z; acc.w = v.w * d2 + bb.w;
    }
    int p = p0;
    for (; p + 1 < p1; p += 2) {
        int2 e0 = g_csr[p], e1 = g_csr[p + 1];
        float w0 = __int_as_float(e0.y), w1 = __int_as_float(e1.y);
        if (active) {
            float4 u0 = h4[(size_t)e0.x * 10 + q];
            float4 u1 = h4[(size_t)e1.x * 10 + q];
            acc.x += w0 * u0.x + w1 * u1.x;
            acc.y += w0 * u0.y + w1 * u1.y;
            acc.z += w0 * u0.z + w1 * u1.z;
            acc.w += w0 * u0.w + w1 * u1.w;
        }
    }
    if (p < p1) {
        int2 e = g_csr[p];
        float w = __int_as_float(e.y);
        if (active) {
            float4 u = h4[(size_t)e.x * 10 + q];
            acc.x += w * u.x; acc.y += w * u.y;
            acc.z += w * u.z; acc.w += w * u.w;
        }
    }
    float m = active ? fmaxf(fmaxf(acc.x, acc.y), fmaxf(acc.z, acc.w)) : -FLT_MAX;
    #pragma unroll
    for (int o = 8; o; o >>= 1) m = fmaxf(m, __shfl_xor_sync(0xffffffffu, m, o, 16));
    float s = active ? (expf(acc.x - m) + expf(acc.y - m) +
                        expf(acc.z - m) + expf(acc.w - m)) : 0.f;
    #pragma unroll
    for (int o = 8; o; o >>= 1) s += __shfl_xor_sync(0xffffffffu, s, o, 16);
    float l = m + logf(s);
    if (active) {
        ((float4*)out)[(size_t)d * 10 + q] =
            make_float4(acc.x - l, acc.y - l, acc.z - l, acc.w - l);
    }
}

// ---------------- launch ------------------------------------------------------
extern "C" void kernel_launch(void* const* d_in, const int* in_sizes, int n_in,
                              void* d_out, int out_size) {
    const float* x    = (const float*)d_in[0];
    const void*  edge = d_in[1];
    const float* W1   = (const float*)d_in[2];
    const float* b1   = (const float*)d_in[3];
    const float* W2   = (const float*)d_in[4];
    const float* b2   = (const float*)d_in[5];
    float*       out  = (float*)d_out;

    cudaFuncSetAttribute(k_mlp, cudaFuncAttributeMaxDynamicSharedMemorySize, MLP_SMEM);

    k_pre      <<<(N_NODES + 255) / 256, 256>>>((const long long*)edge);
    k_edges    <<<(N_EDGES + 255) / 256, 256>>>(edge);
    k_scan1    <<<SCAN_B, 1024>>>();
    k_scan2    <<<1, 128>>>();
    k_scan3    <<<SCAN_B, 1024>>>();
    k_place    <<<(N_EDGES + 255) / 256, 256>>>();
    k_prep_w   <<<(F_IN * F_HID + 48 * F_HID + 255) / 256, 256>>>(W1, W2);
    k_agg1     <<<(N_NODES * 32 + 255) / 256, 256>>>(x);
    k_mlp      <<<(N_NODES + 63) / 64, 256, MLP_SMEM>>>(b1);
    k_layer2   <<<(N_NODES / 2 * 32 + 255) / 256, 256>>>(b2, out);
}

// round 13
// speedup vs baseline: 1.8665x; 1.2771x over previous
#include <cuda_runtime.h>
#include <cuda_fp16.h>
#include <mma.h>
#include <float.h>
#include <cstdint>
using namespace nvcuda;

#define N_NODES 100000
#define N_EDGES 1000000
#define F_IN    128
#define F_HID   256
#define F_OUT   40
#define SCAN_B  98
#define PAD_ROWS 64

// ---------------- scratch ----------------------------------------------------
__device__ int   g_cnt   [N_NODES];
__device__ float g_dinv  [N_NODES];
__device__ int   g_srcA  [N_EDGES];
__device__ int   g_dstA  [N_EDGES];
__device__ int   g_rowptr[N_NODES + 1];
__device__ int   g_cursor[N_NODES];
__device__ __align__(16) int2 g_csr[N_EDGES];     // {src, w as float bits}
__device__ int   g_bsum[SCAN_B];
__device__ __align__(16) __half g_a1h[(size_t)(N_NODES + PAD_ROWS) * F_IN];
__device__ __align__(16) __half g_a1l[(size_t)(N_NODES + PAD_ROWS) * F_IN];
__device__ __align__(16) float g_h2 [(size_t)N_NODES * F_OUT];
__device__ __align__(16) __half g_w1[128 * 256];   // [k][n] fp16 (rounded)
__device__ __align__(16) __half g_w2[256 * 48];    // [k][n48] fp16, n>=40 zero
__device__ int   g_is32 = 0;   // sticky: dtype is fixed across replays

__device__ __forceinline__ void bsplit_h(float a, __half& hi, __half& lo) {
    hi = __float2half_rn(a);
    lo = __float2half_rn(a - __half2float(hi));
}
__device__ __forceinline__ uint32_t pack_h2(__half a, __half b) {
    __half2 t = __halves2half2(a, b);
    return *(uint32_t*)&t;
}

// ---------------- fused: zero counts + weight fp16 prep + dtype probe --------
__global__ void k_pre(const long long* __restrict__ e64,
                      const float* __restrict__ W1,
                      const float* __restrict__ W2) {
    int i = blockIdx.x * blockDim.x + threadIdx.x;
    if (i < N_NODES) g_cnt[i] = 0;
    if (i < F_IN * F_HID) g_w1[i] = __float2half_rn(W1[i]);
    int j = i - F_IN * F_HID;
    if (j >= 0 && j < 48 * F_HID) {
        int k = j / 48, n = j - k * 48;
        g_w2[j] = (n < F_OUT) ? __float2half_rn(W2[(size_t)k * F_OUT + n])
                              : __float2half(0.f);
    }
    if (blockIdx.x == 0) {
        for (int t = threadIdx.x; t < 8192; t += 256) {
            long long v = e64[(long long)t * 122];
            if (v < 0 || v >= N_NODES) g_is32 = 1;   // sticky across replays
        }
    }
}

__global__ void k_edges(const void* __restrict__ edge) {
    int e = blockIdx.x * blockDim.x + threadIdx.x;
    if (e >= N_EDGES) return;
    int s, d;
    if (g_is32) {
        const int* e32 = (const int*)edge;
        s = e32[e];  d = e32[N_EDGES + e];
    } else {
        const long long* e64 = (const long long*)edge;
        s = (int)e64[e];  d = (int)e64[N_EDGES + e];
    }
    g_srcA[e] = s;
    g_dstA[e] = d;
    atomicAdd(&g_cnt[d], 1);
}

// scan stage 1 (+ fused dinv)
__global__ __launch_bounds__(1024) void k_scan1() {
    __shared__ int wsum[32];
    int tid = threadIdx.x, lane = tid & 31, w = tid >> 5;
    int i = blockIdx.x * 1024 + tid;
    int v = 0;
    if (i < N_NODES) {
        v = g_cnt[i];
        g_dinv[i] = rsqrtf((float)(v + 1));
    }
    int r = v;
    #pragma unroll
    for (int o = 16; o; o >>= 1) r += __shfl_xor_sync(0xffffffffu, r, o);
    if (lane == 0) wsum[w] = r;
    __syncthreads();
    if (w == 0) {
        int y = wsum[lane];
        #pragma unroll
        for (int o = 16; o; o >>= 1) y += __shfl_xor_sync(0xffffffffu, y, o);
        if (lane == 0) g_bsum[blockIdx.x] = y;
    }
}

// scan stage 2 folded into stage 3: each block re-scans the 98 block sums
__global__ __launch_bounds__(1024) void k_scan3() {
    __shared__ int wsum[32];
    __shared__ int bwsum[4];
    __shared__ int s_boff;
    int tid = threadIdx.x, lane = tid & 31, w = tid >> 5;

    int bv = 0, bx = 0;
    if (tid < 128) {
        bv = (tid < SCAN_B) ? g_bsum[tid] : 0;
        bx = bv;
        #pragma unroll
        for (int o = 1; o < 32; o <<= 1) {
            int y = __shfl_up_sync(0xffffffffu, bx, o);
            if (lane >= o) bx += y;
        }
        if (lane == 31) bwsum[w] = bx;
    }
    __syncthreads();
    if (tid < 128) {
        int base = 0;
        #pragma unroll
        for (int b = 0; b < 4; b++) base += (b < w) ? bwsum[b] : 0;
        int incl = base + bx;
        if (tid == (int)blockIdx.x) s_boff = incl - bv;
        if (blockIdx.x == 0 && tid == SCAN_B - 1) g_rowptr[N_NODES] = incl;
    }
    __syncthreads();

    int i = blockIdx.x * 1024 + tid;
    int v = (i < N_NODES) ? g_cnt[i] : 0;
    int x = v;
    #pragma unroll
    for (int o = 1; o < 32; o <<= 1) {
        int y = __shfl_up_sync(0xffffffffu, x, o);
        if (lane >= o) x += y;
    }
    if (lane == 31) wsum[w] = x;
    __syncthreads();
    if (w == 0) {
        int y = wsum[lane];
        #pragma unroll
        for (int o = 1; o < 32; o <<= 1) {
            int z = __shfl_up_sync(0xffffffffu, y, o);
            if (lane >= o) y += z;
        }
        wsum[lane] = y;
    }
    __syncthreads();
    if (i < N_NODES) {
        int off = s_boff + x - v + (w > 0 ? wsum[w - 1] : 0);
        g_rowptr[i] = off;
        g_cursor[i] = off;
    }
}

__global__ void k_place() {
    int e = blockIdx.x * blockDim.x + threadIdx.x;
    if (e >= N_EDGES) return;
    int s = g_srcA[e], d = g_dstA[e];
    int pos = atomicAdd(&g_cursor[d], 1);
    float w = g_dinv[s] * g_dinv[d];
    g_csr[pos] = make_int2(s, __float_as_int(w));
}

// ---------------- layer-1 aggregation (CSR, warp per dst) -> fp16 hi/lo ------
__global__ void k_agg1(const float* __restrict__ x) {
    int t    = blockIdx.x * blockDim.x + threadIdx.x;
    int d    = t >> 5;
    int lane = t & 31;
    if (d >= N_NODES) return;
    const float4* x4 = (const float4*)x;
    float dv = g_dinv[d];
    float d2 = dv * dv;
    float4 v = x4[(size_t)d * 32 + lane];
    float4 acc = make_float4(v.x * d2, v.y * d2, v.z * d2, v.w * d2);
    int p0 = g_rowptr[d], p1 = g_rowptr[d + 1];
    int p = p0;
    for (; p + 3 < p1; p += 4) {                 // 4-way MLP
        int2 e0 = g_csr[p],     e1 = g_csr[p + 1];
        int2 e2 = g_csr[p + 2], e3 = g_csr[p + 3];
        float w0 = __int_as_float(e0.y), w1 = __int_as_float(e1.y);
        float w2 = __int_as_float(e2.y), w3 = __int_as_float(e3.y);
        float4 u0 = x4[(size_t)e0.x * 32 + lane];
        float4 u1 = x4[(size_t)e1.x * 32 + lane];
        float4 u2 = x4[(size_t)e2.x * 32 + lane];
        float4 u3 = x4[(size_t)e3.x * 32 + lane];
        acc.x += w0 * u0.x + w1 * u1.x + w2 * u2.x + w3 * u3.x;
        acc.y += w0 * u0.y + w1 * u1.y + w2 * u2.y + w3 * u3.y;
        acc.z += w0 * u0.z + w1 * u1.z + w2 * u2.z + w3 * u3.z;
        acc.w += w0 * u0.w + w1 * u1.w + w2 * u2.w + w3 * u3.w;
    }
    for (; p < p1; p++) {
        int2 e = g_csr[p];
        float w = __int_as_float(e.y);
        float4 u = x4[(size_t)e.x * 32 + lane];
        acc.x += w * u.x; acc.y += w * u.y;
        acc.z += w * u.z; acc.w += w * u.w;
    }
    __half h0, l0, h1, l1, h2, l2, h3, l3;
    bsplit_h(acc.x, h0, l0); bsplit_h(acc.y, h1, l1);
    bsplit_h(acc.z, h2, l2); bsplit_h(acc.w, h3, l3);
    size_t base = (size_t)d * F_IN + lane * 4;
    *(uint32_t*)&g_a1h[base]     = pack_h2(h0, h1);
    *(uint32_t*)&g_a1h[base + 2] = pack_h2(h2, h3);
    *(uint32_t*)&g_a1l[base]     = pack_h2(l0, l1);
    *(uint32_t*)&g_a1l[base + 2] = pack_h2(l2, l3);
}

// ---------------- fused MLP: h2 = relu(agg1@W1+b1) @ W2 ----------------------
// fp16 A-split (2 MMAs: ah*b + al*b), weights plain fp16.
// 64 rows/block, 256 threads, smem staging + LDSM, W1 double-buffered
// 2 k-tiles deep, smem aliasing for 2 CTAs/SM.
#define SM_H    0
#define SM_A    67584
#define MLP_SMEM 102400

__device__ __forceinline__ void stage_b1(char* sm, int buf, int sub, int k, int tid) {
    __half* B = (__half*)(sm + SM_H + buf * 16896 + sub * 8448);
    #pragma unroll
    for (int u = tid; u < 512; u += 256) {
        int r = u >> 5, c8 = (u & 31) << 3;
        *(uint4*)&B[r * 264 + c8] = *(const uint4*)&g_w1[(k * 16 + r) * 256 + c8];
    }
}

__global__ __launch_bounds__(256, 2) void k_mlp(const float* __restrict__ b1) {
    extern __shared__ char sm[];
    __half* Hh = (__half*)(sm + SM_H);
    __half* Hl = (__half*)(sm + SM_H + 33792);
    __half* Ah = (__half*)(sm + SM_A);
    __half* Al = (__half*)(sm + SM_A + 17408);
    float*  stg = (float*)(sm + SM_A);      // aliases A (dead in epilogues)

    int tid = threadIdx.x, wid = tid >> 5, lane = tid & 31;
    int bm = blockIdx.x * 64;
    int rg = wid >> 1, cg = wid & 1;     // 4 row-groups x 2 col-groups

    // ---- load A (64 x 128) hi/lo ----
    for (int u = tid; u < 1024; u += 256) {
        int r = u >> 4, c8 = (u & 15) << 3;
        uint4 vh = make_uint4(0, 0, 0, 0), vl = make_uint4(0, 0, 0, 0);
        int gr = bm + r;
        if (gr < N_NODES) {
            vh = *(const uint4*)&g_a1h[(size_t)gr * F_IN + c8];
            vl = *(const uint4*)&g_a1l[(size_t)gr * F_IN + c8];
        }
        *(uint4*)&Ah[r * 136 + c8] = vh;
        *(uint4*)&Al[r * 136 + c8] = vl;
    }
    stage_b1(sm, 0, 0, 0, tid);
    stage_b1(sm, 0, 1, 1, tid);
    __syncthreads();

    // ---- phase A: H = relu(A @ W1 + b1), W1 double-buffered 2 k-tiles deep --
    wmma::fragment<wmma::accumulator, 16, 16, 16, float> acc[8];
    #pragma unroll
    for (int j = 0; j < 8; j++) wmma::fill_fragment(acc[j], 0.f);

    #pragma unroll
    for (int t2 = 0; t2 < 4; t2++) {              // pairs of k-steps
        int cur = t2 & 1;
        if (t2 < 3) {
            stage_b1(sm, 1 - cur, 0, 2 * t2 + 2, tid);
            stage_b1(sm, 1 - cur, 1, 2 * t2 + 3, tid);
        }
        #pragma unroll
        for (int kk = 0; kk < 2; kk++) {
            int k = 2 * t2 + kk;
            __half* B1 = (__half*)(sm + SM_H + cur * 16896 + kk * 8448);

            wmma::fragment<wmma::matrix_a, 16, 16, 16, __half, wmma::row_major> ah, al;
            wmma::load_matrix_sync(ah, &Ah[(rg * 16) * 136 + k * 16], 136);
            wmma::load_matrix_sync(al, &Al[(rg * 16) * 136 + k * 16], 136);
            #pragma unroll
            for (int j = 0; j < 8; j++) {
                wmma::fragment<wmma::matrix_b, 16, 16, 16, __half, wmma::row_major> bf;
                wmma::load_matrix_sync(bf, &B1[cg * 128 + j * 16], 264);
                wmma::mma_sync(acc[j], ah, bf, acc[j]);
                wmma::mma_sync(acc[j], al, bf, acc[j]);
            }
        }
        __syncthreads();
    }

    // ---- epilogue A: bias + relu + fp16 split -> H smem ----
    #pragma unroll
    for (int j = 0; j < 8; j++) {
        wmma::store_matrix_sync(&stg[wid * 256], acc[j], 16, wmma::mem_row_major);
        __syncwarp();
        int r  = lane >> 1, c0 = (lane & 1) * 8;
        int col = cg * 128 + j * 16 + c0;
        uint32_t hw[4], lw[4];
        #pragma unroll
        for (int e = 0; e < 8; e += 2) {
            float f0 = fmaxf(stg[wid * 256 + r * 16 + c0 + e]     + b1[col + e],     0.f);
            float f1 = fmaxf(stg[wid * 256 + r * 16 + c0 + e + 1] + b1[col + e + 1], 0.f);
            __half h0, l0, h1, l1;
            bsplit_h(f0, h0, l0); bsplit_h(f1, h1, l1);
            hw[e >> 1] = pack_h2(h0, h1);
            lw[e >> 1] = pack_h2(l0, l1);
        }
        int row = rg * 16 + r;
        *(uint4*)&Hh[row * 264 + col] = *(uint4*)hw;
        *(uint4*)&Hl[row * 264 + col] = *(uint4*)lw;
        __syncwarp();
    }
    __syncthreads();

    // ---- phase B: H2 = H @ W2 (N padded to 48: cg0 -> 2 tiles, cg1 -> 1) ----
    int nTiles = (cg == 0) ? 2 : 1;
    wmma::fragment<wmma::accumulator, 16, 16, 16, float> acc2[2];
    #pragma unroll
    for (int j = 0; j < 2; j++) wmma::fill_fragment(acc2[j], 0.f);

    #pragma unroll
    for (int k = 0; k < 16; k++) {
        wmma::fragment<wmma::matrix_a, 16, 16, 16, __half, wmma::row_major> ah, al;
        wmma::load_matrix_sync(ah, &Hh[(rg * 16) * 264 + k * 16], 264);
        wmma::load_matrix_sync(al, &Hl[(rg * 16) * 264 + k * 16], 264);
        for (int j = 0; j < nTiles; j++) {
            int nc = (cg == 0) ? j * 16 : 32;
            wmma::fragment<wmma::matrix_b, 16, 16, 16, __half, wmma::row_major> bf;
            wmma::load_matrix_sync(bf, g_w2 + (k * 16) * 48 + nc, 48);
            wmma::mma_sync(acc2[j], ah, bf, acc2[j]);
            wmma::mma_sync(acc2[j], al, bf, acc2[j]);
        }
    }

    // ---- epilogue B: write h2 (cols < 40) ----
    for (int j = 0; j < nTiles; j++) {
        int ncb = (cg == 0) ? j * 16 : 32;
        wmma::store_matrix_sync(&stg[wid * 256], acc2[j], 16, wmma::mem_row_major);
        __syncwarp();
        int r  = lane >> 1, c0 = (lane & 1) * 8;
        int row = bm + rg * 16 + r;
        int col = ncb + c0;
        if (row < N_NODES && col < F_OUT) {
            float* dst = g_h2 + (size_t)row * F_OUT + col;
            *(float4*)(dst)     = *(float4*)&stg[wid * 256 + r * 16 + c0];
            *(float4*)(dst + 4) = *(float4*)&stg[wid * 256 + r * 16 + c0 + 4];
        }
        __syncwarp();
    }
}

// ---------------- layer-2 aggregation + bias + log_softmax (fused) -----------
// 2 dst per warp (16-lane halves); lanes q<10 own one float4 each.
__global__ void k_layer2(const float* __restrict__ b2, float* __restrict__ out) {
    int t    = blockIdx.x * blockDim.x + threadIdx.x;
    int warp = t >> 5;
    int lane = t & 31;
    int half = lane >> 4;
    int q    = lane & 15;
    int d    = warp * 2 + half;
    const float4* h4 = (const float4*)g_h2;
    bool inb    = d < N_NODES;
    bool active = inb && (q < 10);

    float d2 = 0.f; int p0 = 0, p1 = 0;
    if (inb) {
        float dv = g_dinv[d];
        d2 = dv * dv;
        p0 = g_rowptr[d]; p1 = g_rowptr[d + 1];
    }
    float4 acc = make_float4(0.f, 0.f, 0.f, 0.f);
    if (active) {
        float4 v  = h4[(size_t)d * 10 + q];
        float4 bb = ((const float4*)b2)[q];
        acc.x = v.x * d2 + bb.x; acc.y = v.y * d2 + bb.y;
        acc.z = v.z * d2 + bb.z; acc.w = v.w * d2 + bb.w;
    }
    int p = p0;
    for (; p + 1 < p1; p += 2) {
        int2 e0 = g_csr[p], e1 = g_csr[p + 1];
        float w0 = __int_as_float(e0.y), w1 = __int_as_float(e1.y);
        if (active) {
            float4 u0 = h4[(size_t)e0.x * 10 + q];
            float4 u1 = h4[(size_t)e1.x * 10 + q];
            acc.x += w0 * u0.x + w1 * u1.x;
            acc.y += w0 * u0.y + w1 * u1.y;
            acc.z += w0 * u0.z + w1 * u1.z;
            acc.w += w0 * u0.w + w1 * u1.w;
        }
    }
    if (p < p1) {
        int2 e = g_csr[p];
        float w = __int_as_float(e.y);
        if (active) {
            float4 u = h4[(size_t)e.x * 10 + q];
            acc.x += w * u.x; acc.y += w * u.y;
            acc.z += w * u.z; acc.w += w * u.w;
        }
    }
    float m = active ? fmaxf(fmaxf(acc.x, acc.y), fmaxf(acc.z, acc.w)) : -FLT_MAX;
    #pragma unroll
    for (int o = 8; o; o >>= 1) m = fmaxf(m, __shfl_xor_sync(0xffffffffu, m, o, 16));
    float s = active ? (expf(acc.x - m) + expf(acc.y - m) +
                        expf(acc.z - m) + expf(acc.w - m)) : 0.f;
    #pragma unroll
    for (int o = 8; o; o >>= 1) s += __shfl_xor_sync(0xffffffffu, s, o, 16);
    float l = m + logf(s);
    if (active) {
        ((float4*)out)[(size_t)d * 10 + q] =
            make_float4(acc.x - l, acc.y - l, acc.z - l, acc.w - l);
    }
}

// ---------------- launch ------------------------------------------------------
extern "C" void kernel_launch(void* const* d_in, const int* in_sizes, int n_in,
                              void* d_out, int out_size) {
    const float* x    = (const float*)d_in[0];
    const void*  edge = d_in[1];
    const float* W1   = (const float*)d_in[2];
    const float* b1   = (const float*)d_in[3];
    const float* W2   = (const float*)d_in[4];
    const float* b2   = (const float*)d_in[5];
    float*       out  = (float*)d_out;

    cudaFuncSetAttribute(k_mlp, cudaFuncAttributeMaxDynamicSharedMemorySize, MLP_SMEM);

    k_pre      <<<(N_NODES + 255) / 256, 256>>>((const long long*)edge, W1, W2);
    k_edges    <<<(N_EDGES + 255) / 256, 256>>>(edge);
    k_scan1    <<<SCAN_B, 1024>>>();
    k_scan3    <<<SCAN_B, 1024>>>();
    k_place    <<<(N_EDGES + 255) / 256, 256>>>();
    k_agg1     <<<(N_NODES * 32 + 255) / 256, 256>>>(x);
    k_mlp      <<<(N_NODES + 63) / 64, 256, MLP_SMEM>>>(b1);
    k_layer2   <<<(N_NODES / 2 * 32 + 255) / 256, 256>>>(b2, out);
}

// round 14
// speedup vs baseline: 2.1280x; 1.1401x over previous
#include <cuda_runtime.h>
#include <cuda_fp16.h>
#include <mma.h>
#include <float.h>
#include <cstdint>
using namespace nvcuda;

#define N_NODES 100000
#define N_EDGES 1000000
#define F_IN    128
#define F_HID   256
#define F_OUT   40
#define SCAN_B  98
#define PAD_ROWS 64

// ---------------- scratch ----------------------------------------------------
__device__ int   g_cnt   [N_NODES];
__device__ float g_dinv  [N_NODES];
__device__ int   g_srcA  [N_EDGES];
__device__ int   g_dstA  [N_EDGES];
__device__ int   g_rowptr[N_NODES + 1];
__device__ int   g_cursor[N_NODES];
__device__ __align__(16) int2 g_csr[N_EDGES];     // {src, w as float bits}
__device__ int   g_bsum[SCAN_B];
__device__ __align__(16) __half g_xh [(size_t)N_NODES * F_IN];          // x as fp16
__device__ __align__(16) __half g_a1 [(size_t)(N_NODES + PAD_ROWS) * F_IN];
__device__ __align__(16) float g_h2 [(size_t)N_NODES * F_OUT];
__device__ __align__(16) __half g_w1[128 * 256];   // [k][n] fp16
__device__ __align__(16) __half g_w2[256 * 48];    // [k][n48] fp16, n>=40 zero
__device__ int   g_is32 = 0;   // sticky: dtype is fixed across replays

__device__ __forceinline__ uint32_t pack_h2(__half a, __half b) {
    __half2 t = __halves2half2(a, b);
    return *(uint32_t*)&t;
}

// ---------------- fused: zero counts + weight/x fp16 prep + dtype probe ------
__global__ void k_pre(const long long* __restrict__ e64,
                      const float* __restrict__ x,
                      const float* __restrict__ W1,
                      const float* __restrict__ W2) {
    int i = blockIdx.x * blockDim.x + threadIdx.x;
    int total = gridDim.x * blockDim.x;
    if (i < N_NODES) g_cnt[i] = 0;
    if (i < F_IN * F_HID) g_w1[i] = __float2half_rn(W1[i]);
    int j = i - F_IN * F_HID;
    if (j >= 0 && j < 48 * F_HID) {
        int k = j / 48, n = j - k * 48;
        g_w2[j] = (n < F_OUT) ? __float2half_rn(W2[(size_t)k * F_OUT + n])
                              : __float2half(0.f);
    }
    // x -> fp16 (half2 stores)
    const float2* x2 = (const float2*)x;
    __half2* xh2 = (__half2*)g_xh;
    for (int idx = i; idx < N_NODES * F_IN / 2; idx += total) {
        float2 v = x2[idx];
        xh2[idx] = __floats2half2_rn(v.x, v.y);
    }
    if (blockIdx.x == 0) {
        for (int t = threadIdx.x; t < 8192; t += 256) {
            long long v = e64[(long long)t * 122];
            if (v < 0 || v >= N_NODES) g_is32 = 1;   // sticky across replays
        }
    }
}

__global__ void k_edges(const void* __restrict__ edge) {
    int e = blockIdx.x * blockDim.x + threadIdx.x;
    if (e >= N_EDGES) return;
    int s, d;
    if (g_is32) {
        const int* e32 = (const int*)edge;
        s = e32[e];  d = e32[N_EDGES + e];
    } else {
        const long long* e64 = (const long long*)edge;
        s = (int)e64[e];  d = (int)e64[N_EDGES + e];
    }
    g_srcA[e] = s;
    g_dstA[e] = d;
    atomicAdd(&g_cnt[d], 1);
}

// scan stage 1 (+ fused dinv)
__global__ __launch_bounds__(1024) void k_scan1() {
    __shared__ int wsum[32];
    int tid = threadIdx.x, lane = tid & 31, w = tid >> 5;
    int i = blockIdx.x * 1024 + tid;
    int v = 0;
    if (i < N_NODES) {
        v = g_cnt[i];
        g_dinv[i] = rsqrtf((float)(v + 1));
    }
    int r = v;
    #pragma unroll
    for (int o = 16; o; o >>= 1) r += __shfl_xor_sync(0xffffffffu, r, o);
    if (lane == 0) wsum[w] = r;
    __syncthreads();
    if (w == 0) {
        int y = wsum[lane];
        #pragma unroll
        for (int o = 16; o; o >>= 1) y += __shfl_xor_sync(0xffffffffu, y, o);
        if (lane == 0) g_bsum[blockIdx.x] = y;
    }
}

// scan stage 2 folded into stage 3: each block re-scans the 98 block sums
__global__ __launch_bounds__(1024) void k_scan3() {
    __shared__ int wsum[32];
    __shared__ int bwsum[4];
    __shared__ int s_boff;
    int tid = threadIdx.x, lane = tid & 31, w = tid >> 5;

    int bv = 0, bx = 0;
    if (tid < 128) {
        bv = (tid < SCAN_B) ? g_bsum[tid] : 0;
        bx = bv;
        #pragma unroll
        for (int o = 1; o < 32; o <<= 1) {
            int y = __shfl_up_sync(0xffffffffu, bx, o);
            if (lane >= o) bx += y;
        }
        if (lane == 31) bwsum[w] = bx;
    }
    __syncthreads();
    if (tid < 128) {
        int base = 0;
        #pragma unroll
        for (int b = 0; b < 4; b++) base += (b < w) ? bwsum[b] : 0;
        int incl = base + bx;
        if (tid == (int)blockIdx.x) s_boff = incl - bv;
        if (blockIdx.x == 0 && tid == SCAN_B - 1) g_rowptr[N_NODES] = incl;
    }
    __syncthreads();

    int i = blockIdx.x * 1024 + tid;
    int v = (i < N_NODES) ? g_cnt[i] : 0;
    int x = v;
    #pragma unroll
    for (int o = 1; o < 32; o <<= 1) {
        int y = __shfl_up_sync(0xffffffffu, x, o);
        if (lane >= o) x += y;
    }
    if (lane == 31) wsum[w] = x;
    __syncthreads();
    if (w == 0) {
        int y = wsum[lane];
        #pragma unroll
        for (int o = 1; o < 32; o <<= 1) {
            int z = __shfl_up_sync(0xffffffffu, y, o);
            if (lane >= o) y += z;
        }
        wsum[lane] = y;
    }
    __syncthreads();
    if (i < N_NODES) {
        int off = s_boff + x - v + (w > 0 ? wsum[w - 1] : 0);
        g_rowptr[i] = off;
        g_cursor[i] = off;
    }
}

__global__ void k_place() {
    int e = blockIdx.x * blockDim.x + threadIdx.x;
    if (e >= N_EDGES) return;
    int s = g_srcA[e], d = g_dstA[e];
    int pos = atomicAdd(&g_cursor[d], 1);
    float w = g_dinv[s] * g_dinv[d];
    g_csr[pos] = make_int2(s, __float_as_int(w));
}

// ---------------- layer-1 aggregation (CSR, warp per dst, fp16 gathers) ------
__global__ void k_agg1() {
    int t    = blockIdx.x * blockDim.x + threadIdx.x;
    int d    = t >> 5;
    int lane = t & 31;
    if (d >= N_NODES) return;
    const uint2* xr = (const uint2*)g_xh;   // 4 halves per lane slot

    float dv = g_dinv[d];
    float d2 = dv * dv;
    uint2 sv = xr[(size_t)d * 32 + lane];
    __half2 sp0 = *(__half2*)&sv.x, sp1 = *(__half2*)&sv.y;
    float2 s0 = __half22float2(sp0), s1 = __half22float2(sp1);
    float4 acc = make_float4(s0.x * d2, s0.y * d2, s1.x * d2, s1.y * d2);

    int p0 = g_rowptr[d], p1 = g_rowptr[d + 1];
    int p = p0;
    for (; p + 3 < p1; p += 4) {                 // 4-way MLP
        int2 e0 = g_csr[p],     e1 = g_csr[p + 1];
        int2 e2 = g_csr[p + 2], e3 = g_csr[p + 3];
        float w0 = __int_as_float(e0.y), w1 = __int_as_float(e1.y);
        float w2 = __int_as_float(e2.y), w3 = __int_as_float(e3.y);
        uint2 u0 = xr[(size_t)e0.x * 32 + lane];
        uint2 u1 = xr[(size_t)e1.x * 32 + lane];
        uint2 u2 = xr[(size_t)e2.x * 32 + lane];
        uint2 u3 = xr[(size_t)e3.x * 32 + lane];
        float2 a0 = __half22float2(*(__half2*)&u0.x), b0 = __half22float2(*(__half2*)&u0.y);
        float2 a1 = __half22float2(*(__half2*)&u1.x), b1 = __half22float2(*(__half2*)&u1.y);
        float2 a2 = __half22float2(*(__half2*)&u2.x), b2 = __half22float2(*(__half2*)&u2.y);
        float2 a3 = __half22float2(*(__half2*)&u3.x), b3 = __half22float2(*(__half2*)&u3.y);
        acc.x += w0 * a0.x + w1 * a1.x + w2 * a2.x + w3 * a3.x;
        acc.y += w0 * a0.y + w1 * a1.y + w2 * a2.y + w3 * a3.y;
        acc.z += w0 * b0.x + w1 * b1.x + w2 * b2.x + w3 * b3.x;
        acc.w += w0 * b0.y + w1 * b1.y + w2 * b2.y + w3 * b3.y;
    }
    for (; p < p1; p++) {
        int2 e = g_csr[p];
        float w = __int_as_float(e.y);
        uint2 u = xr[(size_t)e.x * 32 + lane];
        float2 a = __half22float2(*(__half2*)&u.x), b = __half22float2(*(__half2*)&u.y);
        acc.x += w * a.x; acc.y += w * a.y;
        acc.z += w * b.x; acc.w += w * b.y;
    }
    uint2 outw;
    outw.x = pack_h2(__float2half_rn(acc.x), __float2half_rn(acc.y));
    outw.y = pack_h2(__float2half_rn(acc.z), __float2half_rn(acc.w));
    ((uint2*)g_a1)[(size_t)d * 32 + lane] = outw;
}

// ---------------- fused MLP: h2 = relu(agg1@W1+b1) @ W2 ----------------------
// Plain fp16 inputs, fp32 accumulate. 64 rows/block, 256 threads, smem
// staging + LDSM, W1 double-buffered 2 k-tiles deep, smem aliasing 2 CTAs/SM.
#define SM_H    0
#define SM_A    33792
#define MLP_SMEM 51200

__device__ __forceinline__ void stage_b1(char* sm, int buf, int sub, int k, int tid) {
    __half* B = (__half*)(sm + SM_H + buf * 16896 + sub * 8448);
    #pragma unroll
    for (int u = tid; u < 512; u += 256) {
        int r = u >> 5, c8 = (u & 31) << 3;
        *(uint4*)&B[r * 264 + c8] = *(const uint4*)&g_w1[(k * 16 + r) * 256 + c8];
    }
}

__global__ __launch_bounds__(256, 2) void k_mlp(const float* __restrict__ b1) {
    extern __shared__ char sm[];
    __half* Hh = (__half*)(sm + SM_H);
    __half* Ah = (__half*)(sm + SM_A);
    float*  stg = (float*)(sm + SM_A);      // aliases A (dead in epilogues)

    int tid = threadIdx.x, wid = tid >> 5, lane = tid & 31;
    int bm = blockIdx.x * 64;
    int rg = wid >> 1, cg = wid & 1;     // 4 row-groups x 2 col-groups

    // ---- load A (64 x 128 fp16) ----
    for (int u = tid; u < 1024; u += 256) {
        int r = u >> 4, c8 = (u & 15) << 3;
        uint4 v = make_uint4(0, 0, 0, 0);
        int gr = bm + r;
        if (gr < N_NODES) v = *(const uint4*)&g_a1[(size_t)gr * F_IN + c8];
        *(uint4*)&Ah[r * 136 + c8] = v;
    }
    stage_b1(sm, 0, 0, 0, tid);
    stage_b1(sm, 0, 1, 1, tid);
    __syncthreads();

    // ---- phase A: H = relu(A @ W1 + b1), W1 double-buffered 2 k-tiles deep --
    wmma::fragment<wmma::accumulator, 16, 16, 16, float> acc[8];
    #pragma unroll
    for (int j = 0; j < 8; j++) wmma::fill_fragment(acc[j], 0.f);

    #pragma unroll
    for (int t2 = 0; t2 < 4; t2++) {              // pairs of k-steps
        int cur = t2 & 1;
        if (t2 < 3) {
            stage_b1(sm, 1 - cur, 0, 2 * t2 + 2, tid);
            stage_b1(sm, 1 - cur, 1, 2 * t2 + 3, tid);
        }
        #pragma unroll
        for (int kk = 0; kk < 2; kk++) {
            int k = 2 * t2 + kk;
            __half* B1 = (__half*)(sm + SM_H + cur * 16896 + kk * 8448);

            wmma::fragment<wmma::matrix_a, 16, 16, 16, __half, wmma::row_major> af;
            wmma::load_matrix_sync(af, &Ah[(rg * 16) * 136 + k * 16], 136);
            #pragma unroll
            for (int j = 0; j < 8; j++) {
                wmma::fragment<wmma::matrix_b, 16, 16, 16, __half, wmma::row_major> bf;
                wmma::load_matrix_sync(bf, &B1[cg * 128 + j * 16], 264);
                wmma::mma_sync(acc[j], af, bf, acc[j]);
            }
        }
        __syncthreads();
    }

    // ---- epilogue A: bias + relu -> fp16 H smem ----
    #pragma unroll
    for (int j = 0; j < 8; j++) {
        wmma::store_matrix_sync(&stg[wid * 256], acc[j], 16, wmma::mem_row_major);
        __syncwarp();
        int r  = lane >> 1, c0 = (lane & 1) * 8;
        int col = cg * 128 + j * 16 + c0;
        uint32_t hw[4];
        #pragma unroll
        for (int e = 0; e < 8; e += 2) {
            float f0 = fmaxf(stg[wid * 256 + r * 16 + c0 + e]     + b1[col + e],     0.f);
            float f1 = fmaxf(stg[wid * 256 + r * 16 + c0 + e + 1] + b1[col + e + 1], 0.f);
            hw[e >> 1] = pack_h2(__float2half_rn(f0), __float2half_rn(f1));
        }
        int row = rg * 16 + r;
        *(uint4*)&Hh[row * 264 + col] = *(uint4*)hw;
        __syncwarp();
    }
    __syncthreads();

    // ---- phase B: H2 = H @ W2 (N padded to 48: cg0 -> 2 tiles, cg1 -> 1) ----
    int nTiles = (cg == 0) ? 2 : 1;
    wmma::fragment<wmma::accumulator, 16, 16, 16, float> acc2[2];
    #pragma unroll
    for (int j = 0; j < 2; j++) wmma::fill_fragment(acc2[j], 0.f);

    #pragma unroll
    for (int k = 0; k < 16; k++) {
        wmma::fragment<wmma::matrix_a, 16, 16, 16, __half, wmma::row_major> af;
        wmma::load_matrix_sync(af, &Hh[(rg * 16) * 264 + k * 16], 264);
        for (int j = 0; j < nTiles; j++) {
            int nc = (cg == 0) ? j * 16 : 32;
            wmma::fragment<wmma::matrix_b, 16, 16, 16, __half, wmma::row_major> bf;
            wmma::load_matrix_sync(bf, g_w2 + (k * 16) * 48 + nc, 48);
            wmma::mma_sync(acc2[j], af, bf, acc2[j]);
        }
    }

    // ---- epilogue B: write h2 (cols < 40) ----
    for (int j = 0; j < nTiles; j++) {
        int ncb = (cg == 0) ? j * 16 : 32;
        wmma::store_matrix_sync(&stg[wid * 256], acc2[j], 16, wmma::mem_row_major);
        __syncwarp();
        int r  = lane >> 1, c0 = (lane & 1) * 8;
        int row = bm + rg * 16 + r;
        int col = ncb + c0;
        if (row < N_NODES && col < F_OUT) {
            float* dst = g_h2 + (size_t)row * F_OUT + col;
            *(float4*)(dst)     = *(float4*)&stg[wid * 256 + r * 16 + c0];
            *(float4*)(dst + 4) = *(float4*)&stg[wid * 256 + r * 16 + c0 + 4];
        }
        __syncwarp();
    }
}

// ---------------- layer-2 aggregation + bias + log_softmax (fused) -----------
// 2 dst per warp (16-lane halves); lanes q<10 own one float4 each.
__global__ void k_layer2(const float* __restrict__ b2, float* __restrict__ out) {
    int t    = blockIdx.x * blockDim.x + threadIdx.x;
    int warp = t >> 5;
    int lane = t & 31;
    int half = lane >> 4;
    int q    = lane & 15;
    int d    = warp * 2 + half;
    const float4* h4 = (const float4*)g_h2;
    bool inb    = d < N_NODES;
    bool active = inb && (q < 10);

    float d2 = 0.f; int p0 = 0, p1 = 0;
    if (inb) {
        float dv = g_dinv[d];
        d2 = dv * dv;
        p0 = g_rowptr[d]; p1 = g_rowptr[d + 1];
    }
    float4 acc = make_float4(0.f, 0.f, 0.f, 0.f);
    if (active) {
        float4 v  = h4[(size_t)d * 10 + q];
        float4 bb = ((const float4*)b2)[q];
        acc.x = v.x * d2 + bb.x; acc.y = v.y * d2 + bb.y;
        acc.z = v.z * d2 + bb.z; acc.w = v.w * d2 + bb.w;
    }
    int p = p0;
    for (; p + 1 < p1; p += 2) {
        int2 e0 = g_csr[p], e1 = g_csr[p + 1];
        float w0 = __int_as_float(e0.y), w1 = __int_as_float(e1.y);
        if (active) {
            float4 u0 = h4[(size_t)e0.x * 10 + q];
            float4 u1 = h4[(size_t)e1.x * 10 + q];
            acc.x += w0 * u0.x + w1 * u1.x;
            acc.y += w0 * u0.y + w1 * u1.y;
            acc.z += w0 * u0.z + w1 * u1.z;
            acc.w += w0 * u0.w + w1 * u1.w;
        }
    }
    if (p < p1) {
        int2 e = g_csr[p];
        float w = __int_as_float(e.y);
        if (active) {
            float4 u = h4[(size_t)e.x * 10 + q];
            acc.x += w * u.x; acc.y += w * u.y;
            acc.z += w * u.z; acc.w += w * u.w;
        }
    }
    float m = active ? fmaxf(fmaxf(acc.x, acc.y), fmaxf(acc.z, acc.w)) : -FLT_MAX;
    #pragma unroll
    for (int o = 8; o; o >>= 1) m = fmaxf(m, __shfl_xor_sync(0xffffffffu, m, o, 16));
    float s = active ? (expf(acc.x - m) + expf(acc.y - m) +
                        expf(acc.z - m) + expf(acc.w - m)) : 0.f;
    #pragma unroll
    for (int o = 8; o; o >>= 1) s += __shfl_xor_sync(0xffffffffu, s, o, 16);
    float l = m + logf(s);
    if (active) {
        ((float4*)out)[(size_t)d * 10 + q] =
            make_float4(acc.x - l, acc.y - l, acc.z - l, acc.w - l);
    }
}

// ---------------- launch ------------------------------------------------------
extern "C" void kernel_launch(void* const* d_in, const int* in_sizes, int n_in,
                              void* d_out, int out_size) {
    const float* x    = (const float*)d_in[0];
    const void*  edge = d_in[1];
    const float* W1   = (const float*)d_in[2];
    const float* b1   = (const float*)d_in[3];
    const float* W2   = (const float*)d_in[4];
    const float* b2   = (const float*)d_in[5];
    float*       out  = (float*)d_out;

    cudaFuncSetAttribute(k_mlp, cudaFuncAttributeMaxDynamicSharedMemorySize, MLP_SMEM);

    k_pre      <<<(N_NODES + 255) / 256, 256>>>((const long long*)edge, x, W1, W2);
    k_edges    <<<(N_EDGES + 255) / 256, 256>>>(edge);
    k_scan1    <<<SCAN_B, 1024>>>();
    k_scan3    <<<SCAN_B, 1024>>>();
    k_place    <<<(N_EDGES + 255) / 256, 256>>>();
    k_agg1     <<<(N_NODES * 32 + 255) / 256, 256>>>();
    k_mlp      <<<(N_NODES + 63) / 64, 256, MLP_SMEM>>>(b1);
    k_layer2   <<<(N_NODES / 2 * 32 + 255) / 256, 256>>>(b2, out);
}

// round 15
// speedup vs baseline: 2.1972x; 1.0325x over previous
#include <cuda_runtime.h>
#include <cuda_fp16.h>
#include <mma.h>
#include <float.h>
#include <cstdint>
using namespace nvcuda;

#define N_NODES 100000
#define N_EDGES 1000000
#define F_IN    128
#define F_HID   256
#define F_OUT   40
#define SCAN_B  98
#define PAD_ROWS 64

// ---------------- scratch ----------------------------------------------------
__device__ int   g_cnt   [N_NODES];
__device__ float g_dinv  [N_NODES];
__device__ int   g_rowptr[N_NODES + 1];
__device__ int   g_cursor[N_NODES];
__device__ __align__(16) int2 g_csr[N_EDGES];     // {src, w as float bits}
__device__ int   g_bsum[SCAN_B];
__device__ __align__(16) __half g_xh [(size_t)N_NODES * F_IN];          // x as fp16
__device__ __align__(16) __half g_a1 [(size_t)(N_NODES + PAD_ROWS) * F_IN];
__device__ __align__(16) __half g_h2 [(size_t)(N_NODES + 8) * F_OUT];   // fp16 h2
__device__ __align__(16) __half g_w1[128 * 256];   // [k][n] fp16
__device__ __align__(16) __half g_w2[256 * 48];    // [k][n48] fp16, n>=40 zero
__device__ int   g_is32 = 0;   // sticky: dtype is fixed across replays

__device__ __forceinline__ uint32_t pack_h2(__half a, __half b) {
    __half2 t = __halves2half2(a, b);
    return *(uint32_t*)&t;
}

// ---------------- fused: zero counts + weight/x fp16 prep + dtype probe ------
__global__ void k_pre(const long long* __restrict__ e64,
                      const float* __restrict__ x,
                      const float* __restrict__ W1,
                      const float* __restrict__ W2) {
    int i = blockIdx.x * blockDim.x + threadIdx.x;
    int total = gridDim.x * blockDim.x;
    if (i < N_NODES) g_cnt[i] = 0;
    if (i < F_IN * F_HID) g_w1[i] = __float2half_rn(W1[i]);
    int j = i - F_IN * F_HID;
    if (j >= 0 && j < 48 * F_HID) {
        int k = j / 48, n = j - k * 48;
        g_w2[j] = (n < F_OUT) ? __float2half_rn(W2[(size_t)k * F_OUT + n])
                              : __float2half(0.f);
    }
    // x -> fp16 (half2 stores)
    const float2* x2 = (const float2*)x;
    __half2* xh2 = (__half2*)g_xh;
    for (int idx = i; idx < N_NODES * F_IN / 2; idx += total) {
        float2 v = x2[idx];
        xh2[idx] = __floats2half2_rn(v.x, v.y);
    }
    if (blockIdx.x == 0) {
        for (int t = threadIdx.x; t < 8192; t += 256) {
            long long v = e64[(long long)t * 122];
            if (v < 0 || v >= N_NODES) g_is32 = 1;   // sticky across replays
        }
    }
}

// counts only (dst half of edge)
__global__ void k_edges(const void* __restrict__ edge) {
    int e = blockIdx.x * blockDim.x + threadIdx.x;
    if (e >= N_EDGES) return;
    int d;
    if (g_is32) d = ((const int*)edge)[N_EDGES + e];
    else        d = (int)((const long long*)edge)[N_EDGES + e];
    atomicAdd(&g_cnt[d], 1);
}

// scan stage 1 (+ fused dinv)
__global__ __launch_bounds__(1024) void k_scan1() {
    __shared__ int wsum[32];
    int tid = threadIdx.x, lane = tid & 31, w = tid >> 5;
    int i = blockIdx.x * 1024 + tid;
    int v = 0;
    if (i < N_NODES) {
        v = g_cnt[i];
        g_dinv[i] = rsqrtf((float)(v + 1));
    }
    int r = v;
    #pragma unroll
    for (int o = 16; o; o >>= 1) r += __shfl_xor_sync(0xffffffffu, r, o);
    if (lane == 0) wsum[w] = r;
    __syncthreads();
    if (w == 0) {
        int y = wsum[lane];
        #pragma unroll
        for (int o = 16; o; o >>= 1) y += __shfl_xor_sync(0xffffffffu, y, o);
        if (lane == 0) g_bsum[blockIdx.x] = y;
    }
}

// scan stage 2 folded into stage 3: each block re-scans the 98 block sums
__global__ __launch_bounds__(1024) void k_scan3() {
    __shared__ int wsum[32];
    __shared__ int bwsum[4];
    __shared__ int s_boff;
    int tid = threadIdx.x, lane = tid & 31, w = tid >> 5;

    int bv = 0, bx = 0;
    if (tid < 128) {
        bv = (tid < SCAN_B) ? g_bsum[tid] : 0;
        bx = bv;
        #pragma unroll
        for (int o = 1; o < 32; o <<= 1) {
            int y = __shfl_up_sync(0xffffffffu, bx, o);
            if (lane >= o) bx += y;
        }
        if (lane == 31) bwsum[w] = bx;
    }
    __syncthreads();
    if (tid < 128) {
        int base = 0;
        #pragma unroll
        for (int b = 0; b < 4; b++) base += (b < w) ? bwsum[b] : 0;
        int incl = base + bx;
        if (tid == (int)blockIdx.x) s_boff = incl - bv;
        if (blockIdx.x == 0 && tid == SCAN_B - 1) g_rowptr[N_NODES] = incl;
    }
    __syncthreads();

    int i = blockIdx.x * 1024 + tid;
    int v = (i < N_NODES) ? g_cnt[i] : 0;
    int x = v;
    #pragma unroll
    for (int o = 1; o < 32; o <<= 1) {
        int y = __shfl_up_sync(0xffffffffu, x, o);
        if (lane >= o) x += y;
    }
    if (lane == 31) wsum[w] = x;
    __syncthreads();
    if (w == 0) {
        int y = wsum[lane];
        #pragma unroll
        for (int o = 1; o < 32; o <<= 1) {
            int z = __shfl_up_sync(0xffffffffu, y, o);
            if (lane >= o) y += z;
        }
        wsum[lane] = y;
    }
    __syncthreads();
    if (i < N_NODES) {
        int off = s_boff + x - v + (w > 0 ? wsum[w - 1] : 0);
        g_rowptr[i] = off;
        g_cursor[i] = off;
    }
}

// place: read src/dst straight from the input edge buffer
__global__ void k_place(const void* __restrict__ edge) {
    int e = blockIdx.x * blockDim.x + threadIdx.x;
    if (e >= N_EDGES) return;
    int s, d;
    if (g_is32) {
        const int* e32 = (const int*)edge;
        s = e32[e];  d = e32[N_EDGES + e];
    } else {
        const long long* e64 = (const long long*)edge;
        s = (int)e64[e];  d = (int)e64[N_EDGES + e];
    }
    int pos = atomicAdd(&g_cursor[d], 1);
    float w = g_dinv[s] * g_dinv[d];
    g_csr[pos] = make_int2(s, __float_as_int(w));
}

// ---------------- layer-1 aggregation (CSR, warp per dst, fp16 gathers) ------
__global__ void k_agg1() {
    int t    = blockIdx.x * blockDim.x + threadIdx.x;
    int d    = t >> 5;
    int lane = t & 31;
    if (d >= N_NODES) return;
    const uint2* xr = (const uint2*)g_xh;   // 4 halves per lane slot

    float dv = g_dinv[d];
    float d2 = dv * dv;
    uint2 sv = xr[(size_t)d * 32 + lane];
    float2 s0 = __half22float2(*(__half2*)&sv.x), s1 = __half22float2(*(__half2*)&sv.y);
    float4 acc = make_float4(s0.x * d2, s0.y * d2, s1.x * d2, s1.y * d2);

    int p0 = g_rowptr[d], p1 = g_rowptr[d + 1];
    int p = p0;
    for (; p + 3 < p1; p += 4) {                 // 4-way MLP
        int2 e0 = g_csr[p],     e1 = g_csr[p + 1];
        int2 e2 = g_csr[p + 2], e3 = g_csr[p + 3];
        float w0 = __int_as_float(e0.y), w1 = __int_as_float(e1.y);
        float w2 = __int_as_float(e2.y), w3 = __int_as_float(e3.y);
        uint2 u0 = xr[(size_t)e0.x * 32 + lane];
        uint2 u1 = xr[(size_t)e1.x * 32 + lane];
        uint2 u2 = xr[(size_t)e2.x * 32 + lane];
        uint2 u3 = xr[(size_t)e3.x * 32 + lane];
        float2 a0 = __half22float2(*(__half2*)&u0.x), b0 = __half22float2(*(__half2*)&u0.y);
        float2 a1 = __half22float2(*(__half2*)&u1.x), b1 = __half22float2(*(__half2*)&u1.y);
        float2 a2 = __half22float2(*(__half2*)&u2.x), b2 = __half22float2(*(__half2*)&u2.y);
        float2 a3 = __half22float2(*(__half2*)&u3.x), b3 = __half22float2(*(__half2*)&u3.y);
        acc.x += w0 * a0.x + w1 * a1.x + w2 * a2.x + w3 * a3.x;
        acc.y += w0 * a0.y + w1 * a1.y + w2 * a2.y + w3 * a3.y;
        acc.z += w0 * b0.x + w1 * b1.x + w2 * b2.x + w3 * b3.x;
        acc.w += w0 * b0.y + w1 * b1.y + w2 * b2.y + w3 * b3.y;
    }
    for (; p < p1; p++) {
        int2 e = g_csr[p];
        float w = __int_as_float(e.y);
        uint2 u = xr[(size_t)e.x * 32 + lane];
        float2 a = __half22float2(*(__half2*)&u.x), b = __half22float2(*(__half2*)&u.y);
        acc.x += w * a.x; acc.y += w * a.y;
        acc.z += w * b.x; acc.w += w * b.y;
    }
    uint2 outw;
    outw.x = pack_h2(__float2half_rn(acc.x), __float2half_rn(acc.y));
    outw.y = pack_h2(__float2half_rn(acc.z), __float2half_rn(acc.w));
    ((uint2*)g_a1)[(size_t)d * 32 + lane] = outw;
}

// ---------------- fused MLP: h2 = relu(agg1@W1+b1) @ W2 ----------------------
// Plain fp16 inputs, fp32 accumulate, fp16 h2 output.
#define SM_H    0
#define SM_A    33792
#define MLP_SMEM 51200

__device__ __forceinline__ void stage_b1(char* sm, int buf, int sub, int k, int tid) {
    __half* B = (__half*)(sm + SM_H + buf * 16896 + sub * 8448);
    #pragma unroll
    for (int u = tid; u < 512; u += 256) {
        int r = u >> 5, c8 = (u & 31) << 3;
        *(uint4*)&B[r * 264 + c8] = *(const uint4*)&g_w1[(k * 16 + r) * 256 + c8];
    }
}

__global__ __launch_bounds__(256, 2) void k_mlp(const float* __restrict__ b1) {
    extern __shared__ char sm[];
    __half* Hh = (__half*)(sm + SM_H);
    __half* Ah = (__half*)(sm + SM_A);
    float*  stg = (float*)(sm + SM_A);      // aliases A (dead in epilogues)

    int tid = threadIdx.x, wid = tid >> 5, lane = tid & 31;
    int bm = blockIdx.x * 64;
    int rg = wid >> 1, cg = wid & 1;     // 4 row-groups x 2 col-groups

    // ---- load A (64 x 128 fp16) ----
    for (int u = tid; u < 1024; u += 256) {
        int r = u >> 4, c8 = (u & 15) << 3;
        uint4 v = make_uint4(0, 0, 0, 0);
        int gr = bm + r;
        if (gr < N_NODES) v = *(const uint4*)&g_a1[(size_t)gr * F_IN + c8];
        *(uint4*)&Ah[r * 136 + c8] = v;
    }
    stage_b1(sm, 0, 0, 0, tid);
    stage_b1(sm, 0, 1, 1, tid);
    __syncthreads();

    // ---- phase A: H = relu(A @ W1 + b1), W1 double-buffered 2 k-tiles deep --
    wmma::fragment<wmma::accumulator, 16, 16, 16, float> acc[8];
    #pragma unroll
    for (int j = 0; j < 8; j++) wmma::fill_fragment(acc[j], 0.f);

    #pragma unroll
    for (int t2 = 0; t2 < 4; t2++) {              // pairs of k-steps
        int cur = t2 & 1;
        if (t2 < 3) {
            stage_b1(sm, 1 - cur, 0, 2 * t2 + 2, tid);
            stage_b1(sm, 1 - cur, 1, 2 * t2 + 3, tid);
        }
        #pragma unroll
        for (int kk = 0; kk < 2; kk++) {
            int k = 2 * t2 + kk;
            __half* B1 = (__half*)(sm + SM_H + cur * 16896 + kk * 8448);

            wmma::fragment<wmma::matrix_a, 16, 16, 16, __half, wmma::row_major> af;
            wmma::load_matrix_sync(af, &Ah[(rg * 16) * 136 + k * 16], 136);
            #pragma unroll
            for (int j = 0; j < 8; j++) {
                wmma::fragment<wmma::matrix_b, 16, 16, 16, __half, wmma::row_major> bf;
                wmma::load_matrix_sync(bf, &B1[cg * 128 + j * 16], 264);
                wmma::mma_sync(acc[j], af, bf, acc[j]);
            }
        }
        __syncthreads();
    }

    // ---- epilogue A: bias + relu -> fp16 H smem ----
    #pragma unroll
    for (int j = 0; j < 8; j++) {
        wmma::store_matrix_sync(&stg[wid * 256], acc[j], 16, wmma::mem_row_major);
        __syncwarp();
        int r  = lane >> 1, c0 = (lane & 1) * 8;
        int col = cg * 128 + j * 16 + c0;
        uint32_t hw[4];
        #pragma unroll
        for (int e = 0; e < 8; e += 2) {
            float f0 = fmaxf(stg[wid * 256 + r * 16 + c0 + e]     + b1[col + e],     0.f);
            float f1 = fmaxf(stg[wid * 256 + r * 16 + c0 + e + 1] + b1[col + e + 1], 0.f);
            hw[e >> 1] = pack_h2(__float2half_rn(f0), __float2half_rn(f1));
        }
        int row = rg * 16 + r;
        *(uint4*)&Hh[row * 264 + col] = *(uint4*)hw;
        __syncwarp();
    }
    __syncthreads();

    // ---- phase B: H2 = H @ W2 (N padded to 48: cg0 -> 2 tiles, cg1 -> 1) ----
    int nTiles = (cg == 0) ? 2 : 1;
    wmma::fragment<wmma::accumulator, 16, 16, 16, float> acc2[2];
    #pragma unroll
    for (int j = 0; j < 2; j++) wmma::fill_fragment(acc2[j], 0.f);

    #pragma unroll
    for (int k = 0; k < 16; k++) {
        wmma::fragment<wmma::matrix_a, 16, 16, 16, __half, wmma::row_major> af;
        wmma::load_matrix_sync(af, &Hh[(rg * 16) * 264 + k * 16], 264);
        for (int j = 0; j < nTiles; j++) {
            int nc = (cg == 0) ? j * 16 : 32;
            wmma::fragment<wmma::matrix_b, 16, 16, 16, __half, wmma::row_major> bf;
            wmma::load_matrix_sync(bf, g_w2 + (k * 16) * 48 + nc, 48);
            wmma::mma_sync(acc2[j], af, bf, acc2[j]);
        }
    }

    // ---- epilogue B: write fp16 h2 (cols < 40) ----
    for (int j = 0; j < nTiles; j++) {
        int ncb = (cg == 0) ? j * 16 : 32;
        wmma::store_matrix_sync(&stg[wid * 256], acc2[j], 16, wmma::mem_row_major);
        __syncwarp();
        int r  = lane >> 1, c0 = (lane & 1) * 8;
        int row = bm + rg * 16 + r;
        int col = ncb + c0;
        if (row < N_NODES && col < F_OUT) {
            float4 v0 = *(float4*)&stg[wid * 256 + r * 16 + c0];
            float4 v1 = *(float4*)&stg[wid * 256 + r * 16 + c0 + 4];
            uint4 hv;
            hv.x = pack_h2(__float2half_rn(v0.x), __float2half_rn(v0.y));
            hv.y = pack_h2(__float2half_rn(v0.z), __float2half_rn(v0.w));
            hv.z = pack_h2(__float2half_rn(v1.x), __float2half_rn(v1.y));
            hv.w = pack_h2(__float2half_rn(v1.z), __float2half_rn(v1.w));
            *(uint4*)&g_h2[(size_t)row * F_OUT + col] = hv;
        }
        __syncwarp();
    }
}

// ---------------- layer-2 aggregation + bias + log_softmax (fused) -----------
// 2 dst per warp (16-lane halves); lanes q<10 own one uint2 (4 halves) each.
__global__ void k_layer2(const float* __restrict__ b2, float* __restrict__ out) {
    int t    = blockIdx.x * blockDim.x + threadIdx.x;
    int warp = t >> 5;
    int lane = t & 31;
    int half = lane >> 4;
    int q    = lane & 15;
    int d    = warp * 2 + half;
    const uint2* h2r = (const uint2*)g_h2;
    bool inb    = d < N_NODES;
    bool active = inb && (q < 10);

    float d2 = 0.f; int p0 = 0, p1 = 0;
    if (inb) {
        float dv = g_dinv[d];
        d2 = dv * dv;
        p0 = g_rowptr[d]; p1 = g_rowptr[d + 1];
    }
    float4 acc = make_float4(0.f, 0.f, 0.f, 0.f);
    if (active) {
        uint2 sv = h2r[(size_t)d * 10 + q];
        float2 a = __half22float2(*(__half2*)&sv.x), b = __half22float2(*(__half2*)&sv.y);
        float4 bb = ((const float4*)b2)[q];
        acc.x = a.x * d2 + bb.x; acc.y = a.y * d2 + bb.y;
        acc.z = b.x * d2 + bb.z; acc.w = b.y * d2 + bb.w;
    }
    int p = p0;
    for (; p + 1 < p1; p += 2) {
        int2 e0 = g_csr[p], e1 = g_csr[p + 1];
        float w0 = __int_as_float(e0.y), w1 = __int_as_float(e1.y);
        if (active) {
            uint2 u0 = h2r[(size_t)e0.x * 10 + q];
            uint2 u1 = h2r[(size_t)e1.x * 10 + q];
            float2 a0 = __half22float2(*(__half2*)&u0.x), c0 = __half22float2(*(__half2*)&u0.y);
            float2 a1 = __half22float2(*(__half2*)&u1.x), c1 = __half22float2(*(__half2*)&u1.y);
            acc.x += w0 * a0.x + w1 * a1.x;
            acc.y += w0 * a0.y + w1 * a1.y;
            acc.z += w0 * c0.x + w1 * c1.x;
            acc.w += w0 * c0.y + w1 * c1.y;
        }
    }
    if (p < p1) {
        int2 e = g_csr[p];
        float w = __int_as_float(e.y);
        if (active) {
            uint2 u = h2r[(size_t)e.x * 10 + q];
            float2 a = __half22float2(*(__half2*)&u.x), c = __half22float2(*(__half2*)&u.y);
            acc.x += w * a.x; acc.y += w * a.y;
            acc.z += w * c.x; acc.w += w * c.y;
        }
    }
    float m = active ? fmaxf(fmaxf(acc.x, acc.y), fmaxf(acc.z, acc.w)) : -FLT_MAX;
    #pragma unroll
    for (int o = 8; o; o >>= 1) m = fmaxf(m, __shfl_xor_sync(0xffffffffu, m, o, 16));
    float s = active ? (expf(acc.x - m) + expf(acc.y - m) +
                        expf(acc.z - m) + expf(acc.w - m)) : 0.f;
    #pragma unroll
    for (int o = 8; o; o >>= 1) s += __shfl_xor_sync(0xffffffffu, s, o, 16);
    float l = m + logf(s);
    if (active) {
        ((float4*)out)[(size_t)d * 10 + q] =
            make_float4(acc.x - l, acc.y - l, acc.z - l, acc.w - l);
    }
}

// ---------------- launch ------------------------------------------------------
extern "C" void kernel_launch(void* const* d_in, const int* in_sizes, int n_in,
                              void* d_out, int out_size) {
    const float* x    = (const float*)d_in[0];
    const void*  edge = d_in[1];
    const float* W1   = (const float*)d_in[2];
    const float* b1   = (const float*)d_in[3];
    const float* W2   = (const float*)d_in[4];
    const float* b2   = (const float*)d_in[5];
    float*       out  = (float*)d_out;

    cudaFuncSetAttribute(k_mlp, cudaFuncAttributeMaxDynamicSharedMemorySize, MLP_SMEM);

    k_pre      <<<(N_NODES + 255) / 256, 256>>>((const long long*)edge, x, W1, W2);
    k_edges    <<<(N_EDGES + 255) / 256, 256>>>(edge);
    k_scan1    <<<SCAN_B, 1024>>>();
    k_scan3    <<<SCAN_B, 1024>>>();
    k_place    <<<(N_EDGES + 255) / 256, 256>>>(edge);
    k_agg1     <<<(N_NODES * 32 + 255) / 256, 256>>>();
    k_mlp      <<<(N_NODES + 63) / 64, 256, MLP_SMEM>>>(b1);
    k_layer2   <<<(N_NODES / 2 * 32 + 255) / 256, 256>>>(b2, out);
}

// round 16
// speedup vs baseline: 2.3183x; 1.0551x over previous
#include <cuda_runtime.h>
#include <cuda_fp16.h>
#include <mma.h>
#include <float.h>
#include <cstdint>
using namespace nvcuda;

#define N_NODES 100000
#define N_EDGES 1000000
#define F_IN    128
#define F_HID   256
#define F_OUT   40
#define SCAN_B  98
#define PAD_ROWS 64

// ---------------- scratch ----------------------------------------------------
__device__ int   g_cnt   [N_NODES];
__device__ float g_dinv  [N_NODES];
__device__ int   g_rowptr[N_NODES + 1];
__device__ int   g_cursor[N_NODES];
__device__ __align__(16) int2 g_csr[N_EDGES];     // {src, w as float bits}
__device__ int   g_bsum[SCAN_B];
__device__ __align__(16) __half g_xh [(size_t)N_NODES * F_IN];          // x as fp16
__device__ __align__(16) __half g_a1 [(size_t)(N_NODES + PAD_ROWS) * F_IN];
__device__ __align__(16) __half g_h2 [(size_t)(N_NODES + 8) * F_OUT];   // fp16 h2
__device__ __align__(16) __half g_w1[128 * 256];   // [k][n] fp16
__device__ __align__(16) __half g_w2[256 * 48];    // [k][n48] fp16, n>=40 zero
__device__ int   g_is32 = 0;   // sticky: dtype is fixed across replays

__device__ __forceinline__ uint32_t pack_h2(__half a, __half b) {
    __half2 t = __halves2half2(a, b);
    return *(uint32_t*)&t;
}

// ---------------- fused: zero counts + weight fp16 prep + dtype probe --------
__global__ void k_pre(const long long* __restrict__ e64,
                      const float* __restrict__ W1,
                      const float* __restrict__ W2) {
    int i = blockIdx.x * blockDim.x + threadIdx.x;
    if (i < N_NODES) g_cnt[i] = 0;
    if (i < F_IN * F_HID) g_w1[i] = __float2half_rn(W1[i]);
    int j = i - F_IN * F_HID;
    if (j >= 0 && j < 48 * F_HID) {
        int k = j / 48, n = j - k * 48;
        g_w2[j] = (n < F_OUT) ? __float2half_rn(W2[(size_t)k * F_OUT + n])
                              : __float2half(0.f);
    }
    if (blockIdx.x == 0) {
        for (int t = threadIdx.x; t < 8192; t += 256) {
            long long v = e64[(long long)t * 122];
            if (v < 0 || v >= N_NODES) g_is32 = 1;   // sticky across replays
        }
    }
}

// counts (dst half) + x -> fp16 conversion streamed through the idle BW
__global__ void k_edges(const void* __restrict__ edge, const float* __restrict__ x) {
    int e = blockIdx.x * blockDim.x + threadIdx.x;
    if (e < N_EDGES) {
        int d;
        if (g_is32) d = ((const int*)edge)[N_EDGES + e];
        else        d = (int)((const long long*)edge)[N_EDGES + e];
        atomicAdd(&g_cnt[d], 1);
    }
    const float2* x2 = (const float2*)x;
    __half2* xh2 = (__half2*)g_xh;
    int total = gridDim.x * blockDim.x;
    for (int idx = e; idx < N_NODES * F_IN / 2; idx += total) {
        float2 v = x2[idx];
        xh2[idx] = __floats2half2_rn(v.x, v.y);
    }
}

// scan stage 1 (+ fused dinv)
__global__ __launch_bounds__(1024) void k_scan1() {
    __shared__ int wsum[32];
    int tid = threadIdx.x, lane = tid & 31, w = tid >> 5;
    int i = blockIdx.x * 1024 + tid;
    int v = 0;
    if (i < N_NODES) {
        v = g_cnt[i];
        g_dinv[i] = rsqrtf((float)(v + 1));
    }
    int r = v;
    #pragma unroll
    for (int o = 16; o; o >>= 1) r += __shfl_xor_sync(0xffffffffu, r, o);
    if (lane == 0) wsum[w] = r;
    __syncthreads();
    if (w == 0) {
        int y = wsum[lane];
        #pragma unroll
        for (int o = 16; o; o >>= 1) y += __shfl_xor_sync(0xffffffffu, y, o);
        if (lane == 0) g_bsum[blockIdx.x] = y;
    }
}

// scan stage 2 folded into stage 3: each block re-scans the 98 block sums
__global__ __launch_bounds__(1024) void k_scan3() {
    __shared__ int wsum[32];
    __shared__ int bwsum[4];
    __shared__ int s_boff;
    int tid = threadIdx.x, lane = tid & 31, w = tid >> 5;

    int bv = 0, bx = 0;
    if (tid < 128) {
        bv = (tid < SCAN_B) ? g_bsum[tid] : 0;
        bx = bv;
        #pragma unroll
        for (int o = 1; o < 32; o <<= 1) {
            int y = __shfl_up_sync(0xffffffffu, bx, o);
            if (lane >= o) bx += y;
        }
        if (lane == 31) bwsum[w] = bx;
    }
    __syncthreads();
    if (tid < 128) {
        int base = 0;
        #pragma unroll
        for (int b = 0; b < 4; b++) base += (b < w) ? bwsum[b] : 0;
        int incl = base + bx;
        if (tid == (int)blockIdx.x) s_boff = incl - bv;
        if (blockIdx.x == 0 && tid == SCAN_B - 1) g_rowptr[N_NODES] = incl;
    }
    __syncthreads();

    int i = blockIdx.x * 1024 + tid;
    int v = (i < N_NODES) ? g_cnt[i] : 0;
    int x = v;
    #pragma unroll
    for (int o = 1; o < 32; o <<= 1) {
        int y = __shfl_up_sync(0xffffffffu, x, o);
        if (lane >= o) x += y;
    }
    if (lane == 31) wsum[w] = x;
    __syncthreads();
    if (w == 0) {
        int y = wsum[lane];
        #pragma unroll
        for (int o = 1; o < 32; o <<= 1) {
            int z = __shfl_up_sync(0xffffffffu, y, o);
            if (lane >= o) y += z;
        }
        wsum[lane] = y;
    }
    __syncthreads();
    if (i < N_NODES) {
        int off = s_boff + x - v + (w > 0 ? wsum[w - 1] : 0);
        g_rowptr[i] = off;
        g_cursor[i] = off;
    }
}

// place: 2 edges per thread, vectorized src/dst stream reads
__global__ void k_place(const void* __restrict__ edge) {
    int i = blockIdx.x * blockDim.x + threadIdx.x;   // edge pair index
    if (i * 2 >= N_EDGES) return;                     // N_EDGES even
    int s0, d0, s1, d1;
    if (g_is32) {
        const int2* es = (const int2*)edge;
        const int2* ed = (const int2*)((const int*)edge + N_EDGES);
        int2 sv = es[i], dv = ed[i];
        s0 = sv.x; s1 = sv.y; d0 = dv.x; d1 = dv.y;
    } else {
        const longlong2* es = (const longlong2*)edge;
        const longlong2* ed = (const longlong2*)((const long long*)edge + N_EDGES);
        longlong2 sv = es[i], dv = ed[i];
        s0 = (int)sv.x; s1 = (int)sv.y; d0 = (int)dv.x; d1 = (int)dv.y;
    }
    int p0 = atomicAdd(&g_cursor[d0], 1);
    g_csr[p0] = make_int2(s0, __float_as_int(g_dinv[s0] * g_dinv[d0]));
    int p1 = atomicAdd(&g_cursor[d1], 1);
    g_csr[p1] = make_int2(s1, __float_as_int(g_dinv[s1] * g_dinv[d1]));
}

// ---------------- layer-1 aggregation (CSR, warp per dst, fp16 gathers) ------
__global__ void k_agg1() {
    int t    = blockIdx.x * blockDim.x + threadIdx.x;
    int d    = t >> 5;
    int lane = t & 31;
    if (d >= N_NODES) return;
    const uint2* xr = (const uint2*)g_xh;   // 4 halves per lane slot

    float dv = g_dinv[d];
    float d2 = dv * dv;
    uint2 sv = xr[(size_t)d * 32 + lane];
    float2 s0 = __half22float2(*(__half2*)&sv.x), s1 = __half22float2(*(__half2*)&sv.y);
    float4 acc = make_float4(s0.x * d2, s0.y * d2, s1.x * d2, s1.y * d2);

    int p0 = g_rowptr[d], p1 = g_rowptr[d + 1];
    int p = p0;
    for (; p + 7 < p1; p += 8) {                 // 8-way MLP
        int2 ee[8]; uint2 uu[8];
        #pragma unroll
        for (int q = 0; q < 8; q++) ee[q] = g_csr[p + q];
        #pragma unroll
        for (int q = 0; q < 8; q++) uu[q] = xr[(size_t)ee[q].x * 32 + lane];
        #pragma unroll
        for (int q = 0; q < 8; q++) {
            float w = __int_as_float(ee[q].y);
            float2 a = __half22float2(*(__half2*)&uu[q].x);
            float2 b = __half22float2(*(__half2*)&uu[q].y);
            acc.x += w * a.x; acc.y += w * a.y;
            acc.z += w * b.x; acc.w += w * b.y;
        }
    }
    for (; p + 3 < p1; p += 4) {                 // 4-way tail
        int2 ee[4]; uint2 uu[4];
        #pragma unroll
        for (int q = 0; q < 4; q++) ee[q] = g_csr[p + q];
        #pragma unroll
        for (int q = 0; q < 4; q++) uu[q] = xr[(size_t)ee[q].x * 32 + lane];
        #pragma unroll
        for (int q = 0; q < 4; q++) {
            float w = __int_as_float(ee[q].y);
            float2 a = __half22float2(*(__half2*)&uu[q].x);
            float2 b = __half22float2(*(__half2*)&uu[q].y);
            acc.x += w * a.x; acc.y += w * a.y;
            acc.z += w * b.x; acc.w += w * b.y;
        }
    }
    for (; p < p1; p++) {
        int2 e = g_csr[p];
        float w = __int_as_float(e.y);
        uint2 u = xr[(size_t)e.x * 32 + lane];
        float2 a = __half22float2(*(__half2*)&u.x), b = __half22float2(*(__half2*)&u.y);
        acc.x += w * a.x; acc.y += w * a.y;
        acc.z += w * b.x; acc.w += w * b.y;
    }
    uint2 outw;
    outw.x = pack_h2(__float2half_rn(acc.x), __float2half_rn(acc.y));
    outw.y = pack_h2(__float2half_rn(acc.z), __float2half_rn(acc.w));
    ((uint2*)g_a1)[(size_t)d * 32 + lane] = outw;
}

// ---------------- fused MLP: h2 = relu(agg1@W1+b1) @ W2 ----------------------
// Plain fp16 inputs, fp32 accumulate, fp16 h2 output.
#define SM_H    0
#define SM_A    33792
#define MLP_SMEM 51200

__device__ __forceinline__ void stage_b1(char* sm, int buf, int sub, int k, int tid) {
    __half* B = (__half*)(sm + SM_H + buf * 16896 + sub * 8448);
    #pragma unroll
    for (int u = tid; u < 512; u += 256) {
        int r = u >> 5, c8 = (u & 31) << 3;
        *(uint4*)&B[r * 264 + c8] = *(const uint4*)&g_w1[(k * 16 + r) * 256 + c8];
    }
}

__global__ __launch_bounds__(256, 2) void k_mlp(const float* __restrict__ b1) {
    extern __shared__ char sm[];
    __half* Hh = (__half*)(sm + SM_H);
    __half* Ah = (__half*)(sm + SM_A);
    float*  stg = (float*)(sm + SM_A);      // aliases A (dead in epilogues)

    int tid = threadIdx.x, wid = tid >> 5, lane = tid & 31;
    int bm = blockIdx.x * 64;
    int rg = wid >> 1, cg = wid & 1;     // 4 row-groups x 2 col-groups

    // ---- load A (64 x 128 fp16) ----
    for (int u = tid; u < 1024; u += 256) {
        int r = u >> 4, c8 = (u & 15) << 3;
        uint4 v = make_uint4(0, 0, 0, 0);
        int gr = bm + r;
        if (gr < N_NODES) v = *(const uint4*)&g_a1[(size_t)gr * F_IN + c8];
        *(uint4*)&Ah[r * 136 + c8] = v;
    }
    stage_b1(sm, 0, 0, 0, tid);
    stage_b1(sm, 0, 1, 1, tid);
    __syncthreads();

    // ---- phase A: H = relu(A @ W1 + b1), W1 double-buffered 2 k-tiles deep --
    wmma::fragment<wmma::accumulator, 16, 16, 16, float> acc[8];
    #pragma unroll
    for (int j = 0; j < 8; j++) wmma::fill_fragment(acc[j], 0.f);

    #pragma unroll
    for (int t2 = 0; t2 < 4; t2++) {              // pairs of k-steps
        int cur = t2 & 1;
        if (t2 < 3) {
            stage_b1(sm, 1 - cur, 0, 2 * t2 + 2, tid);
            stage_b1(sm, 1 - cur, 1, 2 * t2 + 3, tid);
        }
        #pragma unroll
        for (int kk = 0; kk < 2; kk++) {
            int k = 2 * t2 + kk;
            __half* B1 = (__half*)(sm + SM_H + cur * 16896 + kk * 8448);

            wmma::fragment<wmma::matrix_a, 16, 16, 16, __half, wmma::row_major> af;
            wmma::load_matrix_sync(af, &Ah[(rg * 16) * 136 + k * 16], 136);
            #pragma unroll
            for (int j = 0; j < 8; j++) {
                wmma::fragment<wmma::matrix_b, 16, 16, 16, __half, wmma::row_major> bf;
                wmma::load_matrix_sync(bf, &B1[cg * 128 + j * 16], 264);
                wmma::mma_sync(acc[j], af, bf, acc[j]);
            }
        }
        __syncthreads();
    }

    // ---- epilogue A: bias + relu -> fp16 H smem ----
    #pragma unroll
    for (int j = 0; j < 8; j++) {
        wmma::store_matrix_sync(&stg[wid * 256], acc[j], 16, wmma::mem_row_major);
        __syncwarp();
        int r  = lane >> 1, c0 = (lane & 1) * 8;
        int col = cg * 128 + j * 16 + c0;
        uint32_t hw[4];
        #pragma unroll
        for (int e = 0; e < 8; e += 2) {
            float f0 = fmaxf(stg[wid * 256 + r * 16 + c0 + e]     + b1[col + e],     0.f);
            float f1 = fmaxf(stg[wid * 256 + r * 16 + c0 + e + 1] + b1[col + e + 1], 0.f);
            hw[e >> 1] = pack_h2(__float2half_rn(f0), __float2half_rn(f1));
        }
        int row = rg * 16 + r;
        *(uint4*)&Hh[row * 264 + col] = *(uint4*)hw;
        __syncwarp();
    }
    __syncthreads();

    // ---- phase B: H2 = H @ W2 (N padded to 48: cg0 -> 2 tiles, cg1 -> 1) ----
    int nTiles = (cg == 0) ? 2 : 1;
    wmma::fragment<wmma::accumulator, 16, 16, 16, float> acc2[2];
    #pragma unroll
    for (int j = 0; j < 2; j++) wmma::fill_fragment(acc2[j], 0.f);

    #pragma unroll
    for (int k = 0; k < 16; k++) {
        wmma::fragment<wmma::matrix_a, 16, 16, 16, __half, wmma::row_major> af;
        wmma::load_matrix_sync(af, &Hh[(rg * 16) * 264 + k * 16], 264);
        for (int j = 0; j < nTiles; j++) {
            int nc = (cg == 0) ? j * 16 : 32;
            wmma::fragment<wmma::matrix_b, 16, 16, 16, __half, wmma::row_major> bf;
            wmma::load_matrix_sync(bf, g_w2 + (k * 16) * 48 + nc, 48);
            wmma::mma_sync(acc2[j], af, bf, acc2[j]);
        }
    }

    // ---- epilogue B: write fp16 h2 (cols < 40) ----
    for (int j = 0; j < nTiles; j++) {
        int ncb = (cg == 0) ? j * 16 : 32;
        wmma::store_matrix_sync(&stg[wid * 256], acc2[j], 16, wmma::mem_row_major);
        __syncwarp();
        int r  = lane >> 1, c0 = (lane & 1) * 8;
        int row = bm + rg * 16 + r;
        int col = ncb + c0;
        if (row < N_NODES && col < F_OUT) {
            float4 v0 = *(float4*)&stg[wid * 256 + r * 16 + c0];
            float4 v1 = *(float4*)&stg[wid * 256 + r * 16 + c0 + 4];
            uint4 hv;
            hv.x = pack_h2(__float2half_rn(v0.x), __float2half_rn(v0.y));
            hv.y = pack_h2(__float2half_rn(v0.z), __float2half_rn(v0.w));
            hv.z = pack_h2(__float2half_rn(v1.x), __float2half_rn(v1.y));
            hv.w = pack_h2(__float2half_rn(v1.z), __float2half_rn(v1.w));
            *(uint4*)&g_h2[(size_t)row * F_OUT + col] = hv;
        }
        __syncwarp();
    }
}

// ---------------- layer-2 aggregation + bias + log_softmax (fused) -----------
// 2 dst per warp (16-lane halves); lanes q<10 own one uint2 (4 halves) each.
__global__ void k_layer2(const float* __restrict__ b2, float* __restrict__ out) {
    int t    = blockIdx.x * blockDim.x + threadIdx.x;
    int warp = t >> 5;
    int lane = t & 31;
    int half = lane >> 4;
    int q    = lane & 15;
    int d    = warp * 2 + half;
    const uint2* h2r = (const uint2*)g_h2;
    bool inb    = d < N_NODES;
    bool active = inb && (q < 10);

    float d2 = 0.f; int p0 = 0, p1 = 0;
    if (inb) {
        float dv = g_dinv[d];
        d2 = dv * dv;
        p0 = g_rowptr[d]; p1 = g_rowptr[d + 1];
    }
    float4 acc = make_float4(0.f, 0.f, 0.f, 0.f);
    if (active) {
        uint2 sv = h2r[(size_t)d * 10 + q];
        float2 a = __half22float2(*(__half2*)&sv.x), b = __half22float2(*(__half2*)&sv.y);
        float4 bb = ((const float4*)b2)[q];
        acc.x = a.x * d2 + bb.x; acc.y = a.y * d2 + bb.y;
        acc.z = b.x * d2 + bb.z; acc.w = b.y * d2 + bb.w;
    }
    int p = p0;
    for (; p + 3 < p1; p += 4) {                  // 4-way MLP
        int2 ee[4]; uint2 uu[4];
        #pragma unroll
        for (int qq = 0; qq < 4; qq++) ee[qq] = g_csr[p + qq];
        if (active) {
            #pragma unroll
            for (int qq = 0; qq < 4; qq++) uu[qq] = h2r[(size_t)ee[qq].x * 10 + q];
            #pragma unroll
            for (int qq = 0; qq < 4; qq++) {
                float w = __int_as_float(ee[qq].y);
                float2 a = __half22float2(*(__half2*)&uu[qq].x);
                float2 c = __half22float2(*(__half2*)&uu[qq].y);
                acc.x += w * a.x; acc.y += w * a.y;
                acc.z += w * c.x; acc.w += w * c.y;
            }
        }
    }
    for (; p < p1; p++) {
        int2 e = g_csr[p];
        float w = __int_as_float(e.y);
        if (active) {
            uint2 u = h2r[(size_t)e.x * 10 + q];
            float2 a = __half22float2(*(__half2*)&u.x), c = __half22float2(*(__half2*)&u.y);
            acc.x += w * a.x; acc.y += w * a.y;
            acc.z += w * c.x; acc.w += w * c.y;
        }
    }
    float m = active ? fmaxf(fmaxf(acc.x, acc.y), fmaxf(acc.z, acc.w)) : -FLT_MAX;
    #pragma unroll
    for (int o = 8; o; o >>= 1) m = fmaxf(m, __shfl_xor_sync(0xffffffffu, m, o, 16));
    float s = active ? (expf(acc.x - m) + expf(acc.y - m) +
                        expf(acc.z - m) + expf(acc.w - m)) : 0.f;
    #pragma unroll
    for (int o = 8; o; o >>= 1) s += __shfl_xor_sync(0xffffffffu, s, o, 16);
    float l = m + logf(s);
    if (active) {
        ((float4*)out)[(size_t)d * 10 + q] =
            make_float4(acc.x - l, acc.y - l, acc.z - l, acc.w - l);
    }
}

// ---------------- launch ------------------------------------------------------
extern "C" void kernel_launch(void* const* d_in, const int* in_sizes, int n_in,
                              void* d_out, int out_size) {
    const float* x    = (const float*)d_in[0];
    const void*  edge = d_in[1];
    const float* W1   = (const float*)d_in[2];
    const float* b1   = (const float*)d_in[3];
    const float* W2   = (const float*)d_in[4];
    const float* b2   = (const float*)d_in[5];
    float*       out  = (float*)d_out;

    cudaFuncSetAttribute(k_mlp, cudaFuncAttributeMaxDynamicSharedMemorySize, MLP_SMEM);

    k_pre      <<<(N_NODES + 255) / 256, 256>>>((const long long*)edge, W1, W2);
    k_edges    <<<(N_EDGES + 255) / 256, 256>>>(edge, x);
    k_scan1    <<<SCAN_B, 1024>>>();
    k_scan3    <<<SCAN_B, 1024>>>();
    k_place    <<<(N_EDGES / 2 + 255) / 256, 256>>>(edge);
    k_agg1     <<<(N_NODES * 32 + 255) / 256, 256>>>();
    k_mlp      <<<(N_NODES + 63) / 64, 256, MLP_SMEM>>>(b1);
    k_layer2   <<<(N_NODES / 2 * 32 + 255) / 256, 256>>>(b2, out);
}

// round 17
// speedup vs baseline: 2.3211x; 1.0012x over previous
#include <cuda_runtime.h>
#include <cuda_fp16.h>
#include <mma.h>
#include <float.h>
#include <cstdint>
using namespace nvcuda;

#define N_NODES 100000
#define N_EDGES 1000000
#define F_IN    128
#define F_HID   256
#define F_OUT   40
#define SCAN_B  98
#define PAD_ROWS 64

// ---------------- scratch ----------------------------------------------------
__device__ int   g_cnt   [N_NODES];
__device__ float g_dinv  [N_NODES];
__device__ int   g_rowptr[N_NODES + 1];
__device__ int   g_cursor[N_NODES];
__device__ __align__(16) int2 g_csr[N_EDGES];     // {src, w as float bits}
__device__ int   g_bsum[SCAN_B];
__device__ __align__(16) __half g_xh [(size_t)N_NODES * F_IN];          // x as fp16
__device__ __align__(16) __half g_a1 [(size_t)(N_NODES + PAD_ROWS) * F_IN];
__device__ __align__(16) __half g_h2 [(size_t)(N_NODES + 8) * F_OUT];   // fp16 h2
__device__ __align__(16) __half g_w1[128 * 256];   // [k][n] fp16
__device__ __align__(16) __half g_w2[256 * 48];    // [k][n48] fp16, n>=40 zero
__device__ int   g_is32 = 0;   // sticky: dtype is fixed across replays

__device__ __forceinline__ uint32_t pack_h2(__half a, __half b) {
    __half2 t = __halves2half2(a, b);
    return *(uint32_t*)&t;
}

// ---------------- pre: zero counts + dtype probe ------------------------------
__global__ void k_pre(const long long* __restrict__ e64) {
    int i = blockIdx.x * blockDim.x + threadIdx.x;
    if (i < N_NODES) g_cnt[i] = 0;
    if (blockIdx.x == 0) {
        for (int t = threadIdx.x; t < 8192; t += 256) {
            long long v = e64[(long long)t * 122];
            if (v < 0 || v >= N_NODES) g_is32 = 1;   // sticky across replays
        }
    }
}

// counts (dst half) + x/W fp16 conversion streamed through the idle BW
__global__ void k_edges(const void* __restrict__ edge, const float* __restrict__ x,
                        const float* __restrict__ W1, const float* __restrict__ W2) {
    int e = blockIdx.x * blockDim.x + threadIdx.x;
    if (e < N_EDGES) {
        int d;
        if (g_is32) d = ((const int*)edge)[N_EDGES + e];
        else        d = (int)((const long long*)edge)[N_EDGES + e];
        atomicAdd(&g_cnt[d], 1);
    }
    if (e < F_IN * F_HID) g_w1[e] = __float2half_rn(W1[e]);
    if (e < 48 * F_HID) {
        int k = e / 48, n = e - k * 48;
        g_w2[e] = (n < F_OUT) ? __float2half_rn(W2[(size_t)k * F_OUT + n])
                              : __float2half(0.f);
    }
    const float2* x2 = (const float2*)x;
    __half2* xh2 = (__half2*)g_xh;
    int total = gridDim.x * blockDim.x;
    for (int idx = e; idx < N_NODES * F_IN / 2; idx += total) {
        float2 v = x2[idx];
        xh2[idx] = __floats2half2_rn(v.x, v.y);
    }
}

// scan stage 1 (+ fused dinv)
__global__ __launch_bounds__(1024) void k_scan1() {
    __shared__ int wsum[32];
    int tid = threadIdx.x, lane = tid & 31, w = tid >> 5;
    int i = blockIdx.x * 1024 + tid;
    int v = 0;
    if (i < N_NODES) {
        v = g_cnt[i];
        g_dinv[i] = rsqrtf((float)(v + 1));
    }
    int r = v;
    #pragma unroll
    for (int o = 16; o; o >>= 1) r += __shfl_xor_sync(0xffffffffu, r, o);
    if (lane == 0) wsum[w] = r;
    __syncthreads();
    if (w == 0) {
        int y = wsum[lane];
        #pragma unroll
        for (int o = 16; o; o >>= 1) y += __shfl_xor_sync(0xffffffffu, y, o);
        if (lane == 0) g_bsum[blockIdx.x] = y;
    }
}

// scan stage 2 folded into stage 3: each block re-scans the 98 block sums
__global__ __launch_bounds__(1024) void k_scan3() {
    __shared__ int wsum[32];
    __shared__ int bwsum[4];
    __shared__ int s_boff;
    int tid = threadIdx.x, lane = tid & 31, w = tid >> 5;

    int bv = 0, bx = 0;
    if (tid < 128) {
        bv = (tid < SCAN_B) ? g_bsum[tid] : 0;
        bx = bv;
        #pragma unroll
        for (int o = 1; o < 32; o <<= 1) {
            int y = __shfl_up_sync(0xffffffffu, bx, o);
            if (lane >= o) bx += y;
        }
        if (lane == 31) bwsum[w] = bx;
    }
    __syncthreads();
    if (tid < 128) {
        int base = 0;
        #pragma unroll
        for (int b = 0; b < 4; b++) base += (b < w) ? bwsum[b] : 0;
        int incl = base + bx;
        if (tid == (int)blockIdx.x) s_boff = incl - bv;
        if (blockIdx.x == 0 && tid == SCAN_B - 1) g_rowptr[N_NODES] = incl;
    }
    __syncthreads();

    int i = blockIdx.x * 1024 + tid;
    int v = (i < N_NODES) ? g_cnt[i] : 0;
    int x = v;
    #pragma unroll
    for (int o = 1; o < 32; o <<= 1) {
        int y = __shfl_up_sync(0xffffffffu, x, o);
        if (lane >= o) x += y;
    }
    if (lane == 31) wsum[w] = x;
    __syncthreads();
    if (w == 0) {
        int y = wsum[lane];
        #pragma unroll
        for (int o = 1; o < 32; o <<= 1) {
            int z = __shfl_up_sync(0xffffffffu, y, o);
            if (lane >= o) y += z;
        }
        wsum[lane] = y;
    }
    __syncthreads();
    if (i < N_NODES) {
        int off = s_boff + x - v + (w > 0 ? wsum[w - 1] : 0);
        g_rowptr[i] = off;
        g_cursor[i] = off;
    }
}

// place: 2 edges per thread, vectorized src/dst stream reads
__global__ void k_place(const void* __restrict__ edge) {
    int i = blockIdx.x * blockDim.x + threadIdx.x;   // edge pair index
    if (i * 2 >= N_EDGES) return;                     // N_EDGES even
    int s0, d0, s1, d1;
    if (g_is32) {
        const int2* es = (const int2*)edge;
        const int2* ed = (const int2*)((const int*)edge + N_EDGES);
        int2 sv = es[i], dv = ed[i];
        s0 = sv.x; s1 = sv.y; d0 = dv.x; d1 = dv.y;
    } else {
        const longlong2* es = (const longlong2*)edge;
        const longlong2* ed = (const longlong2*)((const long long*)edge + N_EDGES);
        longlong2 sv = es[i], dv = ed[i];
        s0 = (int)sv.x; s1 = (int)sv.y; d0 = (int)dv.x; d1 = (int)dv.y;
    }
    int p0 = atomicAdd(&g_cursor[d0], 1);
    g_csr[p0] = make_int2(s0, __float_as_int(g_dinv[s0] * g_dinv[d0]));
    int p1 = atomicAdd(&g_cursor[d1], 1);
    g_csr[p1] = make_int2(s1, __float_as_int(g_dinv[s1] * g_dinv[d1]));
}

// ---------------- layer-1 aggregation: 2 dst/warp, 16 lanes x uint4 ----------
__global__ void k_agg1() {
    int t    = blockIdx.x * blockDim.x + threadIdx.x;
    int warp = t >> 5;
    int lane = t & 31;
    int half = lane >> 4;
    int q    = lane & 15;
    int d    = warp * 2 + half;
    if (d >= N_NODES) return;
    const uint4* xr = (const uint4*)g_xh;   // 8 halves per slot, 16 slots/row

    float dv = g_dinv[d];
    float d2 = dv * dv;
    uint4 sv = xr[(size_t)d * 16 + q];
    float2 f0 = __half22float2(*(__half2*)&sv.x);
    float2 f1 = __half22float2(*(__half2*)&sv.y);
    float2 f2 = __half22float2(*(__half2*)&sv.z);
    float2 f3 = __half22float2(*(__half2*)&sv.w);
    float a0 = f0.x * d2, a1 = f0.y * d2, a2 = f1.x * d2, a3 = f1.y * d2;
    float a4 = f2.x * d2, a5 = f2.y * d2, a6 = f3.x * d2, a7 = f3.y * d2;

    int p0 = g_rowptr[d], p1 = g_rowptr[d + 1];
    int p = p0;
    for (; p + 3 < p1; p += 4) {                 // 4-way MLP (16B gathers)
        int2 ee[4]; uint4 uu[4];
        #pragma unroll
        for (int k = 0; k < 4; k++) ee[k] = g_csr[p + k];
        #pragma unroll
        for (int k = 0; k < 4; k++) uu[k] = xr[(size_t)ee[k].x * 16 + q];
        #pragma unroll
        for (int k = 0; k < 4; k++) {
            float w = __int_as_float(ee[k].y);
            float2 g0 = __half22float2(*(__half2*)&uu[k].x);
            float2 g1 = __half22float2(*(__half2*)&uu[k].y);
            float2 g2 = __half22float2(*(__half2*)&uu[k].z);
            float2 g3 = __half22float2(*(__half2*)&uu[k].w);
            a0 += w * g0.x; a1 += w * g0.y; a2 += w * g1.x; a3 += w * g1.y;
            a4 += w * g2.x; a5 += w * g2.y; a6 += w * g3.x; a7 += w * g3.y;
        }
    }
    for (; p < p1; p++) {
        int2 e = g_csr[p];
        float w = __int_as_float(e.y);
        uint4 u = xr[(size_t)e.x * 16 + q];
        float2 g0 = __half22float2(*(__half2*)&u.x);
        float2 g1 = __half22float2(*(__half2*)&u.y);
        float2 g2 = __half22float2(*(__half2*)&u.z);
        float2 g3 = __half22float2(*(__half2*)&u.w);
        a0 += w * g0.x; a1 += w * g0.y; a2 += w * g1.x; a3 += w * g1.y;
        a4 += w * g2.x; a5 += w * g2.y; a6 += w * g3.x; a7 += w * g3.y;
    }
    uint4 outw;
    outw.x = pack_h2(__float2half_rn(a0), __float2half_rn(a1));
    outw.y = pack_h2(__float2half_rn(a2), __float2half_rn(a3));
    outw.z = pack_h2(__float2half_rn(a4), __float2half_rn(a5));
    outw.w = pack_h2(__float2half_rn(a6), __float2half_rn(a7));
    ((uint4*)g_a1)[(size_t)d * 16 + q] = outw;
}

// ---------------- fused MLP: h2 = relu(agg1@W1+b1) @ W2 ----------------------
// Plain fp16 inputs, fp32 accumulate, fp16 h2 output.
#define SM_H    0
#define SM_A    33792
#define MLP_SMEM 51200

__device__ __forceinline__ void stage_b1(char* sm, int buf, int sub, int k, int tid) {
    __half* B = (__half*)(sm + SM_H + buf * 16896 + sub * 8448);
    #pragma unroll
    for (int u = tid; u < 512; u += 256) {
        int r = u >> 5, c8 = (u & 31) << 3;
        *(uint4*)&B[r * 264 + c8] = *(const uint4*)&g_w1[(k * 16 + r) * 256 + c8];
    }
}

__global__ __launch_bounds__(256, 2) void k_mlp(const float* __restrict__ b1) {
    extern __shared__ char sm[];
    __half* Hh = (__half*)(sm + SM_H);
    __half* Ah = (__half*)(sm + SM_A);
    float*  stg = (float*)(sm + SM_A);      // aliases A (dead in epilogues)

    int tid = threadIdx.x, wid = tid >> 5, lane = tid & 31;
    int bm = blockIdx.x * 64;
    int rg = wid >> 1, cg = wid & 1;     // 4 row-groups x 2 col-groups

    // ---- load A (64 x 128 fp16) ----
    for (int u = tid; u < 1024; u += 256) {
        int r = u >> 4, c8 = (u & 15) << 3;
        uint4 v = make_uint4(0, 0, 0, 0);
        int gr = bm + r;
        if (gr < N_NODES) v = *(const uint4*)&g_a1[(size_t)gr * F_IN + c8];
        *(uint4*)&Ah[r * 136 + c8] = v;
    }
    stage_b1(sm, 0, 0, 0, tid);
    stage_b1(sm, 0, 1, 1, tid);
    __syncthreads();

    // ---- phase A: H = relu(A @ W1 + b1), W1 double-buffered 2 k-tiles deep --
    wmma::fragment<wmma::accumulator, 16, 16, 16, float> acc[8];
    #pragma unroll
    for (int j = 0; j < 8; j++) wmma::fill_fragment(acc[j], 0.f);

    #pragma unroll
    for (int t2 = 0; t2 < 4; t2++) {              // pairs of k-steps
        int cur = t2 & 1;
        if (t2 < 3) {
            stage_b1(sm, 1 - cur, 0, 2 * t2 + 2, tid);
            stage_b1(sm, 1 - cur, 1, 2 * t2 + 3, tid);
        }
        #pragma unroll
        for (int kk = 0; kk < 2; kk++) {
            int k = 2 * t2 + kk;
            __half* B1 = (__half*)(sm + SM_H + cur * 16896 + kk * 8448);

            wmma::fragment<wmma::matrix_a, 16, 16, 16, __half, wmma::row_major> af;
            wmma::load_matrix_sync(af, &Ah[(rg * 16) * 136 + k * 16], 136);
            #pragma unroll
            for (int j = 0; j < 8; j++) {
                wmma::fragment<wmma::matrix_b, 16, 16, 16, __half, wmma::row_major> bf;
                wmma::load_matrix_sync(bf, &B1[cg * 128 + j * 16], 264);
                wmma::mma_sync(acc[j], af, bf, acc[j]);
            }
        }
        __syncthreads();
    }

    // ---- epilogue A: bias + relu -> fp16 H smem ----
    #pragma unroll
    for (int j = 0; j < 8; j++) {
        wmma::store_matrix_sync(&stg[wid * 256], acc[j], 16, wmma::mem_row_major);
        __syncwarp();
        int r  = lane >> 1, c0 = (lane & 1) * 8;
        int col = cg * 128 + j * 16 + c0;
        uint32_t hw[4];
        #pragma unroll
        for (int e = 0; e < 8; e += 2) {
            float f0 = fmaxf(stg[wid * 256 + r * 16 + c0 + e]     + b1[col + e],     0.f);
            float f1 = fmaxf(stg[wid * 256 + r * 16 + c0 + e + 1] + b1[col + e + 1], 0.f);
            hw[e >> 1] = pack_h2(__float2half_rn(f0), __float2half_rn(f1));
        }
        int row = rg * 16 + r;
        *(uint4*)&Hh[row * 264 + col] = *(uint4*)hw;
        __syncwarp();
    }
    __syncthreads();

    // ---- phase B: H2 = H @ W2 (N padded to 48: cg0 -> 2 tiles, cg1 -> 1) ----
    int nTiles = (cg == 0) ? 2 : 1;
    wmma::fragment<wmma::accumulator, 16, 16, 16, float> acc2[2];
    #pragma unroll
    for (int j = 0; j < 2; j++) wmma::fill_fragment(acc2[j], 0.f);

    #pragma unroll
    for (int k = 0; k < 16; k++) {
        wmma::fragment<wmma::matrix_a, 16, 16, 16, __half, wmma::row_major> af;
        wmma::load_matrix_sync(af, &Hh[(rg * 16) * 264 + k * 16], 264);
        for (int j = 0; j < nTiles; j++) {
            int nc = (cg == 0) ? j * 16 : 32;
            wmma::fragment<wmma::matrix_b, 16, 16, 16, __half, wmma::row_major> bf;
            wmma::load_matrix_sync(bf, g_w2 + (k * 16) * 48 + nc, 48);
            wmma::mma_sync(acc2[j], af, bf, acc2[j]);
        }
    }

    // ---- epilogue B: write fp16 h2 (cols < 40) ----
    for (int j = 0; j < nTiles; j++) {
        int ncb = (cg == 0) ? j * 16 : 32;
        wmma::store_matrix_sync(&stg[wid * 256], acc2[j], 16, wmma::mem_row_major);
        __syncwarp();
        int r  = lane >> 1, c0 = (lane & 1) * 8;
        int row = bm + rg * 16 + r;
        int col = ncb + c0;
        if (row < N_NODES && col < F_OUT) {
            float4 v0 = *(float4*)&stg[wid * 256 + r * 16 + c0];
            float4 v1 = *(float4*)&stg[wid * 256 + r * 16 + c0 + 4];
            uint4 hv;
            hv.x = pack_h2(__float2half_rn(v0.x), __float2half_rn(v0.y));
            hv.y = pack_h2(__float2half_rn(v0.z), __float2half_rn(v0.w));
            hv.z = pack_h2(__float2half_rn(v1.x), __float2half_rn(v1.y));
            hv.w = pack_h2(__float2half_rn(v1.z), __float2half_rn(v1.w));
            *(uint4*)&g_h2[(size_t)row * F_OUT + col] = hv;
        }
        __syncwarp();
    }
}

// ---------------- layer-2 aggregation + bias + log_softmax (fused) -----------
// 2 dst per warp (16-lane halves); lanes q<10 own one uint2 (4 halves) each.
__global__ void k_layer2(const float* __restrict__ b2, float* __restrict__ out) {
    int t    = blockIdx.x * blockDim.x + threadIdx.x;
    int warp = t >> 5;
    int lane = t & 31;
    int half = lane >> 4;
    int q    = lane & 15;
    int d    = warp * 2 + half;
    const uint2* h2r = (const uint2*)g_h2;
    bool inb    = d < N_NODES;
    bool active = inb && (q < 10);

    float d2 = 0.f; int p0 = 0, p1 = 0;
    if (inb) {
        float dv = g_dinv[d];
        d2 = dv * dv;
        p0 = g_rowptr[d]; p1 = g_rowptr[d + 1];
    }
    float4 acc = make_float4(0.f, 0.f, 0.f, 0.f);
    if (active) {
        uint2 sv = h2r[(size_t)d * 10 + q];
        float2 a = __half22float2(*(__half2*)&sv.x), b = __half22float2(*(__half2*)&sv.y);
        float4 bb = ((const float4*)b2)[q];
        acc.x = a.x * d2 + bb.x; acc.y = a.y * d2 + bb.y;
        acc.z = b.x * d2 + bb.z; acc.w = b.y * d2 + bb.w;
    }
    int p = p0;
    for (; p + 3 < p1; p += 4) {                  // 4-way MLP
        int2 ee[4]; uint2 uu[4];
        #pragma unroll
        for (int qq = 0; qq < 4; qq++) ee[qq] = g_csr[p + qq];
        if (active) {
            #pragma unroll
            for (int qq = 0; qq < 4; qq++) uu[qq] = h2r[(size_t)ee[qq].x * 10 + q];
            #pragma unroll
            for (int qq = 0; qq < 4; qq++) {
                float w = __int_as_float(ee[qq].y);
                float2 a = __half22float2(*(__half2*)&uu[qq].x);
                float2 c = __half22float2(*(__half2*)&uu[qq].y);
                acc.x += w * a.x; acc.y += w * a.y;
                acc.z += w * c.x; acc.w += w * c.y;
            }
        }
    }
    for (; p < p1; p++) {
        int2 e = g_csr[p];
        float w = __int_as_float(e.y);
        if (active) {
            uint2 u = h2r[(size_t)e.x * 10 + q];
            float2 a = __half22float2(*(__half2*)&u.x), c = __half22float2(*(__half2*)&u.y);
            acc.x += w * a.x; acc.y += w * a.y;
            acc.z += w * c.x; acc.w += w * c.y;
        }
    }
    float m = active ? fmaxf(fmaxf(acc.x, acc.y), fmaxf(acc.z, acc.w)) : -FLT_MAX;
    #pragma unroll
    for (int o = 8; o; o >>= 1) m = fmaxf(m, __shfl_xor_sync(0xffffffffu, m, o, 16));
    float s = active ? (expf(acc.x - m) + expf(acc.y - m) +
                        expf(acc.z - m) + expf(acc.w - m)) : 0.f;
    #pragma unroll
    for (int o = 8; o; o >>= 1) s += __shfl_xor_sync(0xffffffffu, s, o, 16);
    float l = m + logf(s);
    if (active) {
        ((float4*)out)[(size_t)d * 10 + q] =
            make_float4(acc.x - l, acc.y - l, acc.z - l, acc.w - l);
    }
}

// ---------------- launch ------------------------------------------------------
extern "C" void kernel_launch(void* const* d_in, const int* in_sizes, int n_in,
                              void* d_out, int out_size) {
    const float* x    = (const float*)d_in[0];
    const void*  edge = d_in[1];
    const float* W1   = (const float*)d_in[2];
    const float* b1   = (const float*)d_in[3];
    const float* W2   = (const float*)d_in[4];
    const float* b2   = (const float*)d_in[5];
    float*       out  = (float*)d_out;

    cudaFuncSetAttribute(k_mlp, cudaFuncAttributeMaxDynamicSharedMemorySize, MLP_SMEM);

    k_pre      <<<(N_NODES + 255) / 256, 256>>>((const long long*)edge);
    k_edges    <<<(N_EDGES + 255) / 256, 256>>>(edge, x, W1, W2);
    k_scan1    <<<SCAN_B, 1024>>>();
    k_scan3    <<<SCAN_B, 1024>>>();
    k_place    <<<(N_EDGES / 2 + 255) / 256, 256>>>(edge);
    k_agg1     <<<(N_NODES / 2 * 32 + 255) / 256, 256>>>();
    k_mlp      <<<(N_NODES + 63) / 64, 256, MLP_SMEM>>>(b1);
    k_layer2   <<<(N_NODES / 2 * 32 + 255) / 256, 256>>>(b2, out);
}